// round 12
// baseline (speedup 1.0000x reference)
#include <cuda_runtime.h>
#include <math.h>
#include <stdint.h>

// ---------------- problem constants ----------------
#define E_        8
#define NTOK      8192
#define D_        1024
#define F_        2816
#define NSLOT     (NTOK * 2)
#define SLOT_PAD  (NSLOT + E_ * 128)   // 17408
#define OUT_ELEMS (NTOK * D_)

#define BK    8                         // K per stage (one m16n8k8 step)
#define NB    3                         // triple buffer, one sync/stage
#define ROWA  136                       // A row pad (mod 32 == 8 -> conflict-free)
#define ROWB1 264                       // GEMM1 B row pad (256 + 8)
#define ROWB2 136                       // GEMM2 B row pad

#define PROBE_ACT (128 * F_)
#define PROBE_Y2  (128 * D_)

// ---------------- static device scratch ----------------
__device__ __align__(128) float g_act[(size_t)SLOT_PAD * F_];
__device__ __align__(128) float g_y2[(size_t)SLOT_PAD * D_];

__device__ int   g_perm_token[SLOT_PAD];
__device__ float g_perm_w[SLOT_PAD];
__device__ int   g_tok_slot[NSLOT];
__device__ int   g_counts[E_];
__device__ int   g_cursor[E_];
__device__ int   g_pad_off[E_ + 1];
__device__ int   g_topk_idx[NSLOT];
__device__ float g_topk_w[NSLOT];
__device__ int   g_flagA;
__device__ int   g_flagB;
__device__ int   g_useMMA;

// ---------------- tf32 mma helpers ----------------
static __device__ __forceinline__ uint32_t f2tf(float v) {
    uint32_t r;
    asm("cvt.rna.tf32.f32 %0, %1;" : "=r"(r) : "f"(v));
    return r;
}
static __device__ __forceinline__ void mma_tf32(float* d, const uint32_t* a, const uint32_t* b) {
    asm volatile("mma.sync.aligned.m16n8k8.row.col.f32.tf32.tf32.f32 "
                 "{%0,%1,%2,%3}, {%4,%5,%6,%7}, {%8,%9}, {%0,%1,%2,%3};"
                 : "+f"(d[0]), "+f"(d[1]), "+f"(d[2]), "+f"(d[3])
                 : "r"(a[0]), "r"(a[1]), "r"(a[2]), "r"(a[3]), "r"(b[0]), "r"(b[1]));
}

__global__ void mma_selftest() {
    if (threadIdx.x >= 32) return;
    uint32_t one = f2tf(1.0f);
    uint32_t a[4] = {one, one, one, one};
    uint32_t b[2] = {one, one};
    float d[4] = {0.f, 0.f, 0.f, 0.f};
    mma_tf32(d, a, b);
    bool ok = (d[0] == 8.f) && (d[1] == 8.f) && (d[2] == 8.f) && (d[3] == 8.f);
    unsigned m = __ballot_sync(0xffffffffu, ok);
    if (threadIdx.x == 0) g_useMMA = (m == 0xffffffffu) ? 1 : 0;
}

// ---------------- init ----------------
__global__ void init_kernel() {
    int i = blockIdx.x * 256 + threadIdx.x;
    if (i < SLOT_PAD) { g_perm_token[i] = -1; g_perm_w[i] = 0.0f; }
    if (i < E_) g_counts[i] = 0;
    if (i == 0) { g_flagA = 0; g_flagB = 0; }
    if (i < PROBE_ACT) g_act[i] = 0.0f;
    if (i < PROBE_Y2)  g_y2[i] = 0.0f;
}

// ---------------- router / scan / fill ----------------
__global__ void router_kernel(const float* __restrict__ x, const float* __restrict__ rw) {
    int t = blockIdx.x;
    const float* xr = x + (size_t)t * D_;
    int lane = threadIdx.x & 31;
    int w    = threadIdx.x >> 5;

    double s = 0.0;
    for (int d = lane; d < D_; d += 32)
        s += (double)xr[d] * (double)rw[d * E_ + w];
    #pragma unroll
    for (int o = 16; o > 0; o >>= 1)
        s += __shfl_down_sync(0xffffffffu, s, o);

    __shared__ double sc[E_];
    if (lane == 0) sc[w] = s;
    __syncthreads();

    if (threadIdx.x == 0) {
        double m = sc[0];
        #pragma unroll
        for (int e = 1; e < E_; e++) m = fmax(m, sc[e]);
        double p[E_], sum = 0.0;
        #pragma unroll
        for (int e = 0; e < E_; e++) { p[e] = exp(sc[e] - m); sum += p[e]; }
        #pragma unroll
        for (int e = 0; e < E_; e++) p[e] /= sum;
        int i0 = 0;
        #pragma unroll
        for (int e = 1; e < E_; e++) if (p[e] > p[i0]) i0 = e;
        int i1 = (i0 == 0) ? 1 : 0;
        #pragma unroll
        for (int e = 0; e < E_; e++) { if (e == i0) continue; if (p[e] > p[i1]) i1 = e; }
        float p0 = (float)p[i0], p1 = (float)p[i1];
        float inv = 1.0f / (p0 + p1);
        g_topk_idx[t * 2 + 0] = i0;  g_topk_idx[t * 2 + 1] = i1;
        g_topk_w[t * 2 + 0] = p0 * inv;  g_topk_w[t * 2 + 1] = p1 * inv;
        atomicAdd(&g_counts[i0], 1);
        atomicAdd(&g_counts[i1], 1);
    }
}

__global__ void scan_kernel() {
    int off = 0;
    #pragma unroll
    for (int e = 0; e < E_; e++) {
        g_pad_off[e] = off;  g_cursor[e] = off;
        off += (g_counts[e] + 127) & ~127;
    }
    g_pad_off[E_] = off;
}

__global__ void fill_kernel() {
    int idx = blockIdx.x * blockDim.x + threadIdx.x;
    if (idx >= NSLOT) return;
    int e    = g_topk_idx[idx];
    int slot = atomicAdd(&g_cursor[e], 1);
    g_perm_token[slot] = idx >> 1;
    g_perm_w[slot]     = g_topk_w[idx];
    g_tok_slot[idx]    = slot;
}

// =====================================================================
// GEMM1 (tf32 mma): act = silu(x@G) * (x@U)
// CTA 128m x 128f. B tile: 256 n-slots = [gate f 0..127 | up f 0..127].
// 8 warps: wm=wid>>1 (32m), wn=wid&1 (64f, gate+up fused).
// =====================================================================
__global__ __launch_bounds__(256)
void gemm1_mma(const float* __restrict__ x,
               const float* __restrict__ gate_w,
               const float* __restrict__ up_w) {
    if (!g_useMMA) return;
    int row0 = blockIdx.y * 128;
    if (row0 >= g_pad_off[E_]) return;
    int e = 0;
    while (e < E_ - 1 && g_pad_off[e + 1] <= row0) e++;
    int f0  = blockIdx.x * 128;
    int tid = threadIdx.x, wid = tid >> 5, lane = tid & 31;
    int wm = wid >> 1, wn = wid & 1;

    __shared__ uint32_t As[NB][BK * ROWA];
    __shared__ uint32_t Bs[NB][BK * ROWB1];

    // A loader: m = tid&127, kq = (tid>>7)*4  (conflict-free STS)
    int am  = tid & 127;
    int akq = (tid >> 7) * 4;
    int tok = g_perm_token[row0 + am];
    bool valid = (tok >= 0);
    const float* pa = x + (size_t)(valid ? tok : 0) * D_ + akq;

    // B loader: bk = tid>>5 (0..7), bn8 = (tid&31)*8 (0..248); two float4 each
    int bk  = tid >> 5;
    int bn8 = (tid & 31) * 8;
    const float* pb = (bn8 < 128)
        ? gate_w + ((size_t)e * D_ + bk) * F_ + f0 + bn8
        : up_w   + ((size_t)e * D_ + bk) * F_ + f0 + (bn8 - 128);

    float accG[2][8][4], accU[2][8][4];
    #pragma unroll
    for (int i = 0; i < 2; i++)
        #pragma unroll
        for (int j = 0; j < 8; j++)
            #pragma unroll
            for (int q = 0; q < 4; q++) { accG[i][j][q] = 0.f; accU[i][j][q] = 0.f; }

    const int NS = D_ / BK;   // 128

    float4 rA, rB0, rB1;
    rA  = valid ? *(const float4*)pa : make_float4(0, 0, 0, 0);
    rB0 = *(const float4*)pb;
    rB1 = *(const float4*)(pb + 4);
    {
        float a4[4] = {rA.x, rA.y, rA.z, rA.w};
        #pragma unroll
        for (int q = 0; q < 4; q++) As[0][(akq + q) * ROWA + am] = f2tf(a4[q]);
        uint4 b0, b1;
        b0.x = f2tf(rB0.x); b0.y = f2tf(rB0.y); b0.z = f2tf(rB0.z); b0.w = f2tf(rB0.w);
        b1.x = f2tf(rB1.x); b1.y = f2tf(rB1.y); b1.z = f2tf(rB1.z); b1.w = f2tf(rB1.w);
        *(uint4*)&Bs[0][bk * ROWB1 + bn8]     = b0;
        *(uint4*)&Bs[0][bk * ROWB1 + bn8 + 4] = b1;
    }
    rA  = valid ? *(const float4*)(pa + BK) : make_float4(0, 0, 0, 0);
    rB0 = *(const float4*)(pb + (size_t)BK * F_);
    rB1 = *(const float4*)(pb + (size_t)BK * F_ + 4);
    __syncthreads();

    #pragma unroll 1
    for (int s = 0; s < NS; s++) {
        int cb = s % NB;
        if (s + 1 < NS) {
            int nb = (s + 1) % NB;
            float a4[4] = {rA.x, rA.y, rA.z, rA.w};
            #pragma unroll
            for (int q = 0; q < 4; q++) As[nb][(akq + q) * ROWA + am] = f2tf(a4[q]);
            uint4 b0, b1;
            b0.x = f2tf(rB0.x); b0.y = f2tf(rB0.y); b0.z = f2tf(rB0.z); b0.w = f2tf(rB0.w);
            b1.x = f2tf(rB1.x); b1.y = f2tf(rB1.y); b1.z = f2tf(rB1.z); b1.w = f2tf(rB1.w);
            *(uint4*)&Bs[nb][bk * ROWB1 + bn8]     = b0;
            *(uint4*)&Bs[nb][bk * ROWB1 + bn8 + 4] = b1;
        }
        if (s + 2 < NS) {
            int k0 = (s + 2) * BK;
            rA  = valid ? *(const float4*)(pa + k0) : make_float4(0, 0, 0, 0);
            rB0 = *(const float4*)(pb + (size_t)k0 * F_);
            rB1 = *(const float4*)(pb + (size_t)k0 * F_ + 4);
        }
        __syncthreads();

        const uint32_t* A = As[cb];
        const uint32_t* B = Bs[cb];
        int lr = lane >> 2;          // 0..7
        int lk = lane & 3;           // 0..3
        uint32_t a[2][4];
        #pragma unroll
        for (int i = 0; i < 2; i++) {
            int m0 = 32 * wm + 16 * i + lr;
            a[i][0] = A[lk * ROWA + m0];
            a[i][1] = A[lk * ROWA + m0 + 8];
            a[i][2] = A[(lk + 4) * ROWA + m0];
            a[i][3] = A[(lk + 4) * ROWA + m0 + 8];
        }
        #pragma unroll
        for (int j = 0; j < 8; j++) {
            int ng = 64 * wn + 8 * j + lr;
            uint32_t bg[2], bu[2];
            bg[0] = B[lk * ROWB1 + ng];
            bg[1] = B[(lk + 4) * ROWB1 + ng];
            bu[0] = B[lk * ROWB1 + ng + 128];
            bu[1] = B[(lk + 4) * ROWB1 + ng + 128];
            #pragma unroll
            for (int i = 0; i < 2; i++) {
                mma_tf32(accG[i][j], a[i], bg);
                mma_tf32(accU[i][j], a[i], bu);
            }
        }
    }

    // epilogue: SwiGLU, fp32 act
    #pragma unroll
    for (int i = 0; i < 2; i++)
        #pragma unroll
        for (int j = 0; j < 8; j++) {
            int fb = f0 + 64 * wn + 8 * j + 2 * (lane & 3);
            #pragma unroll
            for (int h = 0; h < 2; h++) {
                int row = row0 + 32 * wm + 16 * i + (lane >> 2) + 8 * h;
                float g0 = accG[i][j][2 * h + 0], g1 = accG[i][j][2 * h + 1];
                float u0 = accU[i][j][2 * h + 0], u1 = accU[i][j][2 * h + 1];
                float2 o;
                o.x = (g0 / (1.0f + __expf(-g0))) * u0;
                o.y = (g1 / (1.0f + __expf(-g1))) * u1;
                *(float2*)(g_act + (size_t)row * F_ + fb) = o;
            }
        }
}

// =====================================================================
// GEMM2 (tf32 mma): y2 = w * (act @ Wdown)  -- R11 layout, STS fix
// =====================================================================
__global__ __launch_bounds__(256, 2)
void gemm2_mma(const float* __restrict__ down_w) {
    if (!g_useMMA) return;
    int row0 = blockIdx.y * 128;
    if (row0 >= g_pad_off[E_]) return;
    int e = 0;
    while (e < E_ - 1 && g_pad_off[e + 1] <= row0) e++;
    int n0  = blockIdx.x * 128;
    int tid = threadIdx.x, wid = tid >> 5, lane = tid & 31;
    int wm = wid >> 1, wn = wid & 1;

    __shared__ uint32_t As[NB][BK * ROWA];
    __shared__ uint32_t Bs[NB][BK * ROWB2];

    int am  = tid & 127;
    int akq = (tid >> 7) * 4;
    const float* pa = g_act + (size_t)(row0 + am) * F_ + akq;

    int bk  = tid >> 5;
    int bn4 = (tid & 31) * 4;
    const float* pb = down_w + ((size_t)e * F_ + bk) * D_ + n0 + bn4;

    float acc[2][8][4];
    #pragma unroll
    for (int i = 0; i < 2; i++)
        #pragma unroll
        for (int j = 0; j < 8; j++)
            #pragma unroll
            for (int q = 0; q < 4; q++) acc[i][j][q] = 0.f;

    const int NS = F_ / BK;   // 352

    float4 rA, rB;
    rA = *(const float4*)pa;
    rB = *(const float4*)pb;
    {
        float a4[4] = {rA.x, rA.y, rA.z, rA.w};
        #pragma unroll
        for (int q = 0; q < 4; q++) As[0][(akq + q) * ROWA + am] = f2tf(a4[q]);
        uint4 bb;
        bb.x = f2tf(rB.x); bb.y = f2tf(rB.y); bb.z = f2tf(rB.z); bb.w = f2tf(rB.w);
        *(uint4*)&Bs[0][bk * ROWB2 + bn4] = bb;
    }
    rA = *(const float4*)(pa + BK);
    rB = *(const float4*)(pb + (size_t)BK * D_);
    __syncthreads();

    #pragma unroll 1
    for (int s = 0; s < NS; s++) {
        int cb = s % NB;
        if (s + 1 < NS) {
            int nb = (s + 1) % NB;
            float a4[4] = {rA.x, rA.y, rA.z, rA.w};
            #pragma unroll
            for (int q = 0; q < 4; q++) As[nb][(akq + q) * ROWA + am] = f2tf(a4[q]);
            uint4 bb;
            bb.x = f2tf(rB.x); bb.y = f2tf(rB.y); bb.z = f2tf(rB.z); bb.w = f2tf(rB.w);
            *(uint4*)&Bs[nb][bk * ROWB2 + bn4] = bb;
        }
        if (s + 2 < NS) {
            int k0 = (s + 2) * BK;
            rA = *(const float4*)(pa + k0);
            rB = *(const float4*)(pb + (size_t)k0 * D_);
        }
        __syncthreads();

        const uint32_t* A = As[cb];
        const uint32_t* B = Bs[cb];
        int lr = lane >> 2;
        int lk = lane & 3;
        uint32_t a[2][4];
        #pragma unroll
        for (int i = 0; i < 2; i++) {
            int m0 = 32 * wm + 16 * i + lr;
            a[i][0] = A[lk * ROWA + m0];
            a[i][1] = A[lk * ROWA + m0 + 8];
            a[i][2] = A[(lk + 4) * ROWA + m0];
            a[i][3] = A[(lk + 4) * ROWA + m0 + 8];
        }
        #pragma unroll
        for (int j = 0; j < 8; j++) {
            int nn = 64 * wn + 8 * j + lr;
            uint32_t b[2];
            b[0] = B[lk * ROWB2 + nn];
            b[1] = B[(lk + 4) * ROWB2 + nn];
            #pragma unroll
            for (int i = 0; i < 2; i++)
                mma_tf32(acc[i][j], a[i], b);
        }
    }

    #pragma unroll
    for (int i = 0; i < 2; i++)
        #pragma unroll
        for (int h = 0; h < 2; h++) {
            int row = row0 + 32 * wm + 16 * i + (lane >> 2) + 8 * h;
            float w = g_perm_w[row];
            #pragma unroll
            for (int j = 0; j < 8; j++) {
                int nn = n0 + 64 * wn + 8 * j + 2 * (lane & 3);
                float2 v;
                v.x = acc[i][j][2 * h + 0] * w;
                v.y = acc[i][j][2 * h + 1] * w;
                *(float2*)(g_y2 + (size_t)row * D_ + nn) = v;
            }
        }
}

// ---------------- probes ----------------
__global__ void probeA_kernel() {
    int i = blockIdx.x * 256 + threadIdx.x;
    if (i >= PROBE_ACT) return;
    if (((const uint32_t*)g_act)[i] != 0) g_flagA = 1;
}
__global__ void probeB_kernel() {
    int i = blockIdx.x * 256 + threadIdx.x;
    if (i >= PROBE_Y2) return;
    if (((const uint32_t*)g_y2)[i] != 0) g_flagB = 1;
}

// ---------------- SIMT fallbacks (fp32 insurance) ----------------
#define SBM 64
#define SBN 64
#define SBK 16

__global__ __launch_bounds__(256)
void gemm1_simt(const float* __restrict__ x,
                const float* __restrict__ gate_w,
                const float* __restrict__ up_w) {
    if (g_flagA) return;
    int row0 = blockIdx.y * SBM;
    if (row0 >= g_pad_off[E_]) return;
    int e = 0;
    while (e < E_ - 1 && g_pad_off[e + 1] <= row0) e++;
    const float* G = gate_w + (size_t)e * D_ * F_;
    const float* U = up_w   + (size_t)e * D_ * F_;
    int n0 = blockIdx.x * SBN;

    __shared__ float As2[SBK][SBM + 4];
    __shared__ float Bg[SBK][SBN];
    __shared__ float Bu[SBK][SBN];

    int tid   = threadIdx.x;
    int a_row = tid >> 2;
    int a_k   = (tid & 3) * 4;
    int tok   = g_perm_token[row0 + a_row];
    bool valid = (tok >= 0);
    const float* xrow = x + (size_t)(valid ? tok : 0) * D_;

    int b_k = tid >> 4;
    int b_n = (tid & 15) * 4;
    int ty = tid >> 4, tx = tid & 15;

    float ag[4][4] = {}, au[4][4] = {};

    for (int k0 = 0; k0 < D_; k0 += SBK) {
        float4 av = valid ? *(const float4*)(xrow + k0 + a_k)
                          : make_float4(0.f, 0.f, 0.f, 0.f);
        As2[a_k + 0][a_row] = av.x;  As2[a_k + 1][a_row] = av.y;
        As2[a_k + 2][a_row] = av.z;  As2[a_k + 3][a_row] = av.w;
        *(float4*)&Bg[b_k][b_n] = *(const float4*)(G + (size_t)(k0 + b_k) * F_ + n0 + b_n);
        *(float4*)&Bu[b_k][b_n] = *(const float4*)(U + (size_t)(k0 + b_k) * F_ + n0 + b_n);
        __syncthreads();
        #pragma unroll
        for (int kk = 0; kk < SBK; kk++) {
            float4 a4 = *(const float4*)&As2[kk][ty * 4];
            float4 g4 = *(const float4*)&Bg[kk][tx * 4];
            float4 u4 = *(const float4*)&Bu[kk][tx * 4];
            float am[4] = {a4.x, a4.y, a4.z, a4.w};
            float gm[4] = {g4.x, g4.y, g4.z, g4.w};
            float um[4] = {u4.x, u4.y, u4.z, u4.w};
            #pragma unroll
            for (int i = 0; i < 4; i++)
                #pragma unroll
                for (int j = 0; j < 4; j++) {
                    ag[i][j] += am[i] * gm[j];
                    au[i][j] += am[i] * um[j];
                }
        }
        __syncthreads();
    }

    #pragma unroll
    for (int i = 0; i < 4; i++) {
        int r = row0 + ty * 4 + i;
        size_t base = (size_t)r * F_ + n0 + tx * 4;
        #pragma unroll
        for (int j = 0; j < 4; j++) {
            float g = ag[i][j], u = au[i][j];
            g_act[base + j] = (g / (1.0f + __expf(-g))) * u;
        }
    }
}

__global__ __launch_bounds__(256)
void gemm2_simt(const float* __restrict__ down_w) {
    if (g_flagB) return;
    int row0 = blockIdx.y * SBM;
    if (row0 >= g_pad_off[E_]) return;
    int e = 0;
    while (e < E_ - 1 && g_pad_off[e + 1] <= row0) e++;
    const float* Wd = down_w + (size_t)e * F_ * D_;
    int n0 = blockIdx.x * SBN;

    __shared__ float As2[SBK][SBM + 4];
    __shared__ float Bs2[SBK][SBN];

    int tid   = threadIdx.x;
    int a_row = tid >> 2;
    int a_k   = (tid & 3) * 4;
    size_t abase = (size_t)(row0 + a_row) * F_;

    int b_k = tid >> 4;
    int b_n = (tid & 15) * 4;
    int ty = tid >> 4, tx = tid & 15;

    float acc[4][4] = {};

    for (int k0 = 0; k0 < F_; k0 += SBK) {
        float4 av = *(const float4*)(g_act + abase + k0 + a_k);
        As2[a_k + 0][a_row] = av.x;  As2[a_k + 1][a_row] = av.y;
        As2[a_k + 2][a_row] = av.z;  As2[a_k + 3][a_row] = av.w;
        *(float4*)&Bs2[b_k][b_n] = *(const float4*)(Wd + (size_t)(k0 + b_k) * D_ + n0 + b_n);
        __syncthreads();
        #pragma unroll
        for (int kk = 0; kk < SBK; kk++) {
            float4 a4 = *(const float4*)&As2[kk][ty * 4];
            float4 b4 = *(const float4*)&Bs2[kk][tx * 4];
            float am[4] = {a4.x, a4.y, a4.z, a4.w};
            float bm[4] = {b4.x, b4.y, b4.z, b4.w};
            #pragma unroll
            for (int i = 0; i < 4; i++)
                #pragma unroll
                for (int j = 0; j < 4; j++)
                    acc[i][j] += am[i] * bm[j];
        }
        __syncthreads();
    }

    #pragma unroll
    for (int i = 0; i < 4; i++) {
        int r = row0 + ty * 4 + i;
        float w = g_perm_w[r];
        float* yrow = g_y2 + (size_t)r * D_ + n0 + tx * 4;
        #pragma unroll
        for (int j = 0; j < 4; j++)
            yrow[j] = acc[i][j] * w;
    }
}

// ---------------- combine ----------------
__global__ void combine_kernel(float* __restrict__ out) {
    int i = blockIdx.x * 256 + threadIdx.x;
    if (i >= OUT_ELEMS) return;
    int t = i >> 10, d = i & 1023;
    int s0 = g_tok_slot[t * 2 + 0];
    int s1 = g_tok_slot[t * 2 + 1];
    out[i] = g_y2[(size_t)s0 * D_ + d] + g_y2[(size_t)s1 * D_ + d];
}

// ---------------- launch ----------------
extern "C" void kernel_launch(void* const* d_in, const int* in_sizes, int n_in,
                              void* d_out, int out_size) {
    const float* x      = (const float*)d_in[0];
    const float* rw     = (const float*)d_in[1];
    const float* gate_w = (const float*)d_in[2];
    const float* up_w   = (const float*)d_in[3];
    const float* down_w = (const float*)d_in[4];
    float* out = (float*)d_out;

    mma_selftest<<<1, 32>>>();
    init_kernel<<<(PROBE_ACT + 255) / 256, 256>>>();
    router_kernel<<<NTOK, 256>>>(x, rw);
    scan_kernel<<<1, 1>>>();
    fill_kernel<<<(NSLOT + 255) / 256, 256>>>();

    dim3 g1m(F_ / 128, SLOT_PAD / 128);  // 22 x 136
    gemm1_mma<<<g1m, 256>>>(x, gate_w, up_w);
    probeA_kernel<<<(PROBE_ACT + 255) / 256, 256>>>();
    dim3 g1s(F_ / SBN, SLOT_PAD / SBM);
    gemm1_simt<<<g1s, 256>>>(x, gate_w, up_w);

    dim3 g2m(D_ / 128, SLOT_PAD / 128);  // 8 x 136
    gemm2_mma<<<g2m, 256>>>(down_w);
    probeB_kernel<<<(PROBE_Y2 + 255) / 256, 256>>>();
    dim3 g2s(D_ / SBN, SLOT_PAD / SBM);
    gemm2_simt<<<g2s, 256>>>(down_w);

    combine_kernel<<<(OUT_ELEMS + 255) / 256, 256>>>(out);
}

// round 13
// speedup vs baseline: 1.0467x; 1.0467x over previous
#include <cuda_runtime.h>
#include <math.h>
#include <stdint.h>

// ---------------- problem constants ----------------
#define E_        8
#define NTOK      8192
#define D_        1024
#define F_        2816
#define NSLOT     (NTOK * 2)
#define SLOT_PAD  (NSLOT + E_ * 128)   // 17408
#define OUT_ELEMS (NTOK * D_)

#define BK   8                          // K per stage (one m16n8k8 step)
#define NB   3                          // triple buffer, one sync/stage
#define ROWW 136                        // padded words per k-row (bank-exact)

#define PROBE_ACT (128 * F_)
#define PROBE_Y2  (128 * D_)

// ---------------- static device scratch ----------------
__device__ __align__(128) float g_act[(size_t)SLOT_PAD * F_];
__device__ __align__(128) float g_y2[(size_t)SLOT_PAD * D_];

__device__ int   g_perm_token[SLOT_PAD];
__device__ float g_perm_w[SLOT_PAD];
__device__ int   g_tok_slot[NSLOT];
__device__ int   g_counts[E_];
__device__ int   g_cursor[E_];
__device__ int   g_pad_off[E_ + 1];
__device__ int   g_topk_idx[NSLOT];
__device__ float g_topk_w[NSLOT];
__device__ int   g_flagA;
__device__ int   g_flagB;
__device__ int   g_useMMA;

// ---------------- tf32 mma helpers ----------------
static __device__ __forceinline__ uint32_t f2tf(float v) {
    uint32_t r;
    asm("cvt.rna.tf32.f32 %0, %1;" : "=r"(r) : "f"(v));
    return r;
}
static __device__ __forceinline__ void mma_tf32(float* d, const uint32_t* a, const uint32_t* b) {
    asm volatile("mma.sync.aligned.m16n8k8.row.col.f32.tf32.tf32.f32 "
                 "{%0,%1,%2,%3}, {%4,%5,%6,%7}, {%8,%9}, {%0,%1,%2,%3};"
                 : "+f"(d[0]), "+f"(d[1]), "+f"(d[2]), "+f"(d[3])
                 : "r"(a[0]), "r"(a[1]), "r"(a[2]), "r"(a[3]), "r"(b[0]), "r"(b[1]));
}

__global__ void mma_selftest() {
    if (threadIdx.x >= 32) return;
    uint32_t one = f2tf(1.0f);
    uint32_t a[4] = {one, one, one, one};
    uint32_t b[2] = {one, one};
    float d[4] = {0.f, 0.f, 0.f, 0.f};
    mma_tf32(d, a, b);
    bool ok = (d[0] == 8.f) && (d[1] == 8.f) && (d[2] == 8.f) && (d[3] == 8.f);
    unsigned m = __ballot_sync(0xffffffffu, ok);
    if (threadIdx.x == 0) g_useMMA = (m == 0xffffffffu) ? 1 : 0;
}

// ---------------- init ----------------
__global__ void init_kernel() {
    int i = blockIdx.x * 256 + threadIdx.x;
    if (i < SLOT_PAD) { g_perm_token[i] = -1; g_perm_w[i] = 0.0f; }
    if (i < E_) g_counts[i] = 0;
    if (i == 0) { g_flagA = 0; g_flagB = 0; }
    if (i < PROBE_ACT) g_act[i] = 0.0f;
    if (i < PROBE_Y2)  g_y2[i] = 0.0f;
}

// ---------------- router / scan / fill ----------------
__global__ void router_kernel(const float* __restrict__ x, const float* __restrict__ rw) {
    int t = blockIdx.x;
    const float* xr = x + (size_t)t * D_;
    int lane = threadIdx.x & 31;
    int w    = threadIdx.x >> 5;

    double s = 0.0;
    for (int d = lane; d < D_; d += 32)
        s += (double)xr[d] * (double)rw[d * E_ + w];
    #pragma unroll
    for (int o = 16; o > 0; o >>= 1)
        s += __shfl_down_sync(0xffffffffu, s, o);

    __shared__ double sc[E_];
    if (lane == 0) sc[w] = s;
    __syncthreads();

    if (threadIdx.x == 0) {
        double m = sc[0];
        #pragma unroll
        for (int e = 1; e < E_; e++) m = fmax(m, sc[e]);
        double p[E_], sum = 0.0;
        #pragma unroll
        for (int e = 0; e < E_; e++) { p[e] = exp(sc[e] - m); sum += p[e]; }
        #pragma unroll
        for (int e = 0; e < E_; e++) p[e] /= sum;
        int i0 = 0;
        #pragma unroll
        for (int e = 1; e < E_; e++) if (p[e] > p[i0]) i0 = e;
        int i1 = (i0 == 0) ? 1 : 0;
        #pragma unroll
        for (int e = 0; e < E_; e++) { if (e == i0) continue; if (p[e] > p[i1]) i1 = e; }
        float p0 = (float)p[i0], p1 = (float)p[i1];
        float inv = 1.0f / (p0 + p1);
        g_topk_idx[t * 2 + 0] = i0;  g_topk_idx[t * 2 + 1] = i1;
        g_topk_w[t * 2 + 0] = p0 * inv;  g_topk_w[t * 2 + 1] = p1 * inv;
        atomicAdd(&g_counts[i0], 1);
        atomicAdd(&g_counts[i1], 1);
    }
}

__global__ void scan_kernel() {
    int off = 0;
    #pragma unroll
    for (int e = 0; e < E_; e++) {
        g_pad_off[e] = off;  g_cursor[e] = off;
        off += (g_counts[e] + 127) & ~127;
    }
    g_pad_off[E_] = off;
}

__global__ void fill_kernel() {
    int idx = blockIdx.x * blockDim.x + threadIdx.x;
    if (idx >= NSLOT) return;
    int e    = g_topk_idx[idx];
    int slot = atomicAdd(&g_cursor[e], 1);
    g_perm_token[slot] = idx >> 1;
    g_perm_w[slot]     = g_topk_w[idx];
    g_tok_slot[idx]    = slot;
}

// =====================================================================
// GEMM1 (tf32 mma): act = silu(x@G) * (x@U)  -- R11 geometry + STS fix
// CTA 128m x 64f (gate+up in 128 n-slots). warps: wm=wid>>1, wn=wid&1.
// =====================================================================
__global__ __launch_bounds__(256, 2)
void gemm1_mma(const float* __restrict__ x,
               const float* __restrict__ gate_w,
               const float* __restrict__ up_w) {
    if (!g_useMMA) return;
    int row0 = blockIdx.y * 128;
    if (row0 >= g_pad_off[E_]) return;
    int e = 0;
    while (e < E_ - 1 && g_pad_off[e + 1] <= row0) e++;
    int f0  = blockIdx.x * 64;
    int tid = threadIdx.x, wid = tid >> 5, lane = tid & 31;
    int wm = wid >> 1, wn = wid & 1;

    __shared__ uint32_t As[NB][BK * ROWW];
    __shared__ uint32_t Bs[NB][BK * ROWW];

    // A loader (conflict-free STS): m = tid&127, kq = (tid>>7)*4
    int am  = tid & 127;
    int akq = (tid >> 7) * 4;
    int tok = g_perm_token[row0 + am];
    bool valid = (tok >= 0);
    const float* pa = x + (size_t)(valid ? tok : 0) * D_ + akq;

    // B loader: bk = tid>>5, n4 = (tid&31)*4 (0..124; <64 gate, >=64 up)
    int bk = tid >> 5;
    int bn4 = (tid & 31) * 4;
    const float* pb = (bn4 < 64)
        ? gate_w + ((size_t)e * D_ + bk) * F_ + f0 + bn4
        : up_w   + ((size_t)e * D_ + bk) * F_ + f0 + (bn4 - 64);

    float accG[2][4][4], accU[2][4][4];
    #pragma unroll
    for (int i = 0; i < 2; i++)
        #pragma unroll
        for (int j = 0; j < 4; j++)
            #pragma unroll
            for (int q = 0; q < 4; q++) { accG[i][j][q] = 0.f; accU[i][j][q] = 0.f; }

    const int NS = D_ / BK;   // 128

    float4 rA, rB;
    rA = valid ? *(const float4*)pa : make_float4(0, 0, 0, 0);
    rB = *(const float4*)pb;
    {
        float a4[4] = {rA.x, rA.y, rA.z, rA.w};
        #pragma unroll
        for (int q = 0; q < 4; q++) As[0][(akq + q) * ROWW + am] = f2tf(a4[q]);
        uint4 bb;
        bb.x = f2tf(rB.x); bb.y = f2tf(rB.y); bb.z = f2tf(rB.z); bb.w = f2tf(rB.w);
        *(uint4*)&Bs[0][bk * ROWW + bn4] = bb;
    }
    rA = valid ? *(const float4*)(pa + BK) : make_float4(0, 0, 0, 0);
    rB = *(const float4*)(pb + (size_t)BK * F_);
    __syncthreads();

    #pragma unroll 1
    for (int s = 0; s < NS; s++) {
        int cb = s % NB;
        if (s + 1 < NS) {
            int nb = (s + 1) % NB;
            float a4[4] = {rA.x, rA.y, rA.z, rA.w};
            #pragma unroll
            for (int q = 0; q < 4; q++) As[nb][(akq + q) * ROWW + am] = f2tf(a4[q]);
            uint4 bb;
            bb.x = f2tf(rB.x); bb.y = f2tf(rB.y); bb.z = f2tf(rB.z); bb.w = f2tf(rB.w);
            *(uint4*)&Bs[nb][bk * ROWW + bn4] = bb;
        }
        if (s + 2 < NS) {
            int k0 = (s + 2) * BK;
            rA = valid ? *(const float4*)(pa + k0) : make_float4(0, 0, 0, 0);
            rB = *(const float4*)(pb + (size_t)k0 * F_);
        }
        __syncthreads();

        const uint32_t* A = As[cb];
        const uint32_t* B = Bs[cb];
        int lr = lane >> 2;          // 0..7
        int lk = lane & 3;           // 0..3
        uint32_t a[2][4];
        #pragma unroll
        for (int i = 0; i < 2; i++) {
            int m0 = 32 * wm + 16 * i + lr;
            a[i][0] = A[lk * ROWW + m0];
            a[i][1] = A[lk * ROWW + m0 + 8];
            a[i][2] = A[(lk + 4) * ROWW + m0];
            a[i][3] = A[(lk + 4) * ROWW + m0 + 8];
        }
        #pragma unroll
        for (int j = 0; j < 4; j++) {
            int ng = 32 * wn + 8 * j + lr;
            uint32_t bg[2], bu[2];
            bg[0] = B[lk * ROWW + ng];
            bg[1] = B[(lk + 4) * ROWW + ng];
            bu[0] = B[lk * ROWW + ng + 64];
            bu[1] = B[(lk + 4) * ROWW + ng + 64];
            #pragma unroll
            for (int i = 0; i < 2; i++) {
                mma_tf32(accG[i][j], a[i], bg);
                mma_tf32(accU[i][j], a[i], bu);
            }
        }
    }

    // epilogue: SwiGLU, fp32 act
    #pragma unroll
    for (int i = 0; i < 2; i++)
        #pragma unroll
        for (int j = 0; j < 4; j++) {
            int fb = f0 + 32 * wn + 8 * j + 2 * (lane & 3);
            #pragma unroll
            for (int h = 0; h < 2; h++) {
                int row = row0 + 32 * wm + 16 * i + (lane >> 2) + 8 * h;
                float g0 = accG[i][j][2 * h + 0], g1 = accG[i][j][2 * h + 1];
                float u0 = accU[i][j][2 * h + 0], u1 = accU[i][j][2 * h + 1];
                float2 o;
                o.x = (g0 / (1.0f + __expf(-g0))) * u0;
                o.y = (g1 / (1.0f + __expf(-g1))) * u1;
                *(float2*)(g_act + (size_t)row * F_ + fb) = o;
            }
        }
}

// =====================================================================
// GEMM2 (tf32 mma): y2 = w * (act @ Wdown)  -- R12 version (kept)
// =====================================================================
__global__ __launch_bounds__(256, 2)
void gemm2_mma(const float* __restrict__ down_w) {
    if (!g_useMMA) return;
    int row0 = blockIdx.y * 128;
    if (row0 >= g_pad_off[E_]) return;
    int e = 0;
    while (e < E_ - 1 && g_pad_off[e + 1] <= row0) e++;
    int n0  = blockIdx.x * 128;
    int tid = threadIdx.x, wid = tid >> 5, lane = tid & 31;
    int wm = wid >> 1, wn = wid & 1;

    __shared__ uint32_t As[NB][BK * ROWW];
    __shared__ uint32_t Bs[NB][BK * ROWW];

    int am  = tid & 127;
    int akq = (tid >> 7) * 4;
    const float* pa = g_act + (size_t)(row0 + am) * F_ + akq;

    int bk  = tid >> 5;
    int bn4 = (tid & 31) * 4;
    const float* pb = down_w + ((size_t)e * F_ + bk) * D_ + n0 + bn4;

    float acc[2][8][4];
    #pragma unroll
    for (int i = 0; i < 2; i++)
        #pragma unroll
        for (int j = 0; j < 8; j++)
            #pragma unroll
            for (int q = 0; q < 4; q++) acc[i][j][q] = 0.f;

    const int NS = F_ / BK;   // 352

    float4 rA, rB;
    rA = *(const float4*)pa;
    rB = *(const float4*)pb;
    {
        float a4[4] = {rA.x, rA.y, rA.z, rA.w};
        #pragma unroll
        for (int q = 0; q < 4; q++) As[0][(akq + q) * ROWW + am] = f2tf(a4[q]);
        uint4 bb;
        bb.x = f2tf(rB.x); bb.y = f2tf(rB.y); bb.z = f2tf(rB.z); bb.w = f2tf(rB.w);
        *(uint4*)&Bs[0][bk * ROWW + bn4] = bb;
    }
    rA = *(const float4*)(pa + BK);
    rB = *(const float4*)(pb + (size_t)BK * D_);
    __syncthreads();

    #pragma unroll 1
    for (int s = 0; s < NS; s++) {
        int cb = s % NB;
        if (s + 1 < NS) {
            int nb = (s + 1) % NB;
            float a4[4] = {rA.x, rA.y, rA.z, rA.w};
            #pragma unroll
            for (int q = 0; q < 4; q++) As[nb][(akq + q) * ROWW + am] = f2tf(a4[q]);
            uint4 bb;
            bb.x = f2tf(rB.x); bb.y = f2tf(rB.y); bb.z = f2tf(rB.z); bb.w = f2tf(rB.w);
            *(uint4*)&Bs[nb][bk * ROWW + bn4] = bb;
        }
        if (s + 2 < NS) {
            int k0 = (s + 2) * BK;
            rA = *(const float4*)(pa + k0);
            rB = *(const float4*)(pb + (size_t)k0 * D_);
        }
        __syncthreads();

        const uint32_t* A = As[cb];
        const uint32_t* B = Bs[cb];
        int lr = lane >> 2;
        int lk = lane & 3;
        uint32_t a[2][4];
        #pragma unroll
        for (int i = 0; i < 2; i++) {
            int m0 = 32 * wm + 16 * i + lr;
            a[i][0] = A[lk * ROWW + m0];
            a[i][1] = A[lk * ROWW + m0 + 8];
            a[i][2] = A[(lk + 4) * ROWW + m0];
            a[i][3] = A[(lk + 4) * ROWW + m0 + 8];
        }
        #pragma unroll
        for (int j = 0; j < 8; j++) {
            int nn = 64 * wn + 8 * j + lr;
            uint32_t b[2];
            b[0] = B[lk * ROWW + nn];
            b[1] = B[(lk + 4) * ROWW + nn];
            #pragma unroll
            for (int i = 0; i < 2; i++)
                mma_tf32(acc[i][j], a[i], b);
        }
    }

    #pragma unroll
    for (int i = 0; i < 2; i++)
        #pragma unroll
        for (int h = 0; h < 2; h++) {
            int row = row0 + 32 * wm + 16 * i + (lane >> 2) + 8 * h;
            float w = g_perm_w[row];
            #pragma unroll
            for (int j = 0; j < 8; j++) {
                int nn = n0 + 64 * wn + 8 * j + 2 * (lane & 3);
                float2 v;
                v.x = acc[i][j][2 * h + 0] * w;
                v.y = acc[i][j][2 * h + 1] * w;
                *(float2*)(g_y2 + (size_t)row * D_ + nn) = v;
            }
        }
}

// ---------------- probes ----------------
__global__ void probeA_kernel() {
    int i = blockIdx.x * 256 + threadIdx.x;
    if (i >= PROBE_ACT) return;
    if (((const uint32_t*)g_act)[i] != 0) g_flagA = 1;
}
__global__ void probeB_kernel() {
    int i = blockIdx.x * 256 + threadIdx.x;
    if (i >= PROBE_Y2) return;
    if (((const uint32_t*)g_y2)[i] != 0) g_flagB = 1;
}

// ---------------- SIMT fallbacks (fp32 insurance) ----------------
#define SBM 64
#define SBN 64
#define SBK 16

__global__ __launch_bounds__(256)
void gemm1_simt(const float* __restrict__ x,
                const float* __restrict__ gate_w,
                const float* __restrict__ up_w) {
    if (g_flagA) return;
    int row0 = blockIdx.y * SBM;
    if (row0 >= g_pad_off[E_]) return;
    int e = 0;
    while (e < E_ - 1 && g_pad_off[e + 1] <= row0) e++;
    const float* G = gate_w + (size_t)e * D_ * F_;
    const float* U = up_w   + (size_t)e * D_ * F_;
    int n0 = blockIdx.x * SBN;

    __shared__ float As2[SBK][SBM + 4];
    __shared__ float Bg[SBK][SBN];
    __shared__ float Bu[SBK][SBN];

    int tid   = threadIdx.x;
    int a_row = tid >> 2;
    int a_k   = (tid & 3) * 4;
    int tok   = g_perm_token[row0 + a_row];
    bool valid = (tok >= 0);
    const float* xrow = x + (size_t)(valid ? tok : 0) * D_;

    int b_k = tid >> 4;
    int b_n = (tid & 15) * 4;
    int ty = tid >> 4, tx = tid & 15;

    float ag[4][4] = {}, au[4][4] = {};

    for (int k0 = 0; k0 < D_; k0 += SBK) {
        float4 av = valid ? *(const float4*)(xrow + k0 + a_k)
                          : make_float4(0.f, 0.f, 0.f, 0.f);
        As2[a_k + 0][a_row] = av.x;  As2[a_k + 1][a_row] = av.y;
        As2[a_k + 2][a_row] = av.z;  As2[a_k + 3][a_row] = av.w;
        *(float4*)&Bg[b_k][b_n] = *(const float4*)(G + (size_t)(k0 + b_k) * F_ + n0 + b_n);
        *(float4*)&Bu[b_k][b_n] = *(const float4*)(U + (size_t)(k0 + b_k) * F_ + n0 + b_n);
        __syncthreads();
        #pragma unroll
        for (int kk = 0; kk < SBK; kk++) {
            float4 a4 = *(const float4*)&As2[kk][ty * 4];
            float4 g4 = *(const float4*)&Bg[kk][tx * 4];
            float4 u4 = *(const float4*)&Bu[kk][tx * 4];
            float am[4] = {a4.x, a4.y, a4.z, a4.w};
            float gm[4] = {g4.x, g4.y, g4.z, g4.w};
            float um[4] = {u4.x, u4.y, u4.z, u4.w};
            #pragma unroll
            for (int i = 0; i < 4; i++)
                #pragma unroll
                for (int j = 0; j < 4; j++) {
                    ag[i][j] += am[i] * gm[j];
                    au[i][j] += am[i] * um[j];
                }
        }
        __syncthreads();
    }

    #pragma unroll
    for (int i = 0; i < 4; i++) {
        int r = row0 + ty * 4 + i;
        size_t base = (size_t)r * F_ + n0 + tx * 4;
        #pragma unroll
        for (int j = 0; j < 4; j++) {
            float g = ag[i][j], u = au[i][j];
            g_act[base + j] = (g / (1.0f + __expf(-g))) * u;
        }
    }
}

__global__ __launch_bounds__(256)
void gemm2_simt(const float* __restrict__ down_w) {
    if (g_flagB) return;
    int row0 = blockIdx.y * SBM;
    if (row0 >= g_pad_off[E_]) return;
    int e = 0;
    while (e < E_ - 1 && g_pad_off[e + 1] <= row0) e++;
    const float* Wd = down_w + (size_t)e * F_ * D_;
    int n0 = blockIdx.x * SBN;

    __shared__ float As2[SBK][SBM + 4];
    __shared__ float Bs2[SBK][SBN];

    int tid   = threadIdx.x;
    int a_row = tid >> 2;
    int a_k   = (tid & 3) * 4;
    size_t abase = (size_t)(row0 + a_row) * F_;

    int b_k = tid >> 4;
    int b_n = (tid & 15) * 4;
    int ty = tid >> 4, tx = tid & 15;

    float acc[4][4] = {};

    for (int k0 = 0; k0 < F_; k0 += SBK) {
        float4 av = *(const float4*)(g_act + abase + k0 + a_k);
        As2[a_k + 0][a_row] = av.x;  As2[a_k + 1][a_row] = av.y;
        As2[a_k + 2][a_row] = av.z;  As2[a_k + 3][a_row] = av.w;
        *(float4*)&Bs2[b_k][b_n] = *(const float4*)(Wd + (size_t)(k0 + b_k) * D_ + n0 + b_n);
        __syncthreads();
        #pragma unroll
        for (int kk = 0; kk < SBK; kk++) {
            float4 a4 = *(const float4*)&As2[kk][ty * 4];
            float4 b4 = *(const float4*)&Bs2[kk][tx * 4];
            float am[4] = {a4.x, a4.y, a4.z, a4.w};
            float bm[4] = {b4.x, b4.y, b4.z, b4.w};
            #pragma unroll
            for (int i = 0; i < 4; i++)
                #pragma unroll
                for (int j = 0; j < 4; j++)
                    acc[i][j] += am[i] * bm[j];
        }
        __syncthreads();
    }

    #pragma unroll
    for (int i = 0; i < 4; i++) {
        int r = row0 + ty * 4 + i;
        float w = g_perm_w[r];
        float* yrow = g_y2 + (size_t)r * D_ + n0 + tx * 4;
        #pragma unroll
        for (int j = 0; j < 4; j++)
            yrow[j] = acc[i][j] * w;
    }
}

// ---------------- combine ----------------
__global__ void combine_kernel(float* __restrict__ out) {
    int i = blockIdx.x * 256 + threadIdx.x;
    if (i >= OUT_ELEMS) return;
    int t = i >> 10, d = i & 1023;
    int s0 = g_tok_slot[t * 2 + 0];
    int s1 = g_tok_slot[t * 2 + 1];
    out[i] = g_y2[(size_t)s0 * D_ + d] + g_y2[(size_t)s1 * D_ + d];
}

// ---------------- launch ----------------
extern "C" void kernel_launch(void* const* d_in, const int* in_sizes, int n_in,
                              void* d_out, int out_size) {
    const float* x      = (const float*)d_in[0];
    const float* rw     = (const float*)d_in[1];
    const float* gate_w = (const float*)d_in[2];
    const float* up_w   = (const float*)d_in[3];
    const float* down_w = (const float*)d_in[4];
    float* out = (float*)d_out;

    mma_selftest<<<1, 32>>>();
    init_kernel<<<(PROBE_ACT + 255) / 256, 256>>>();
    router_kernel<<<NTOK, 256>>>(x, rw);
    scan_kernel<<<1, 1>>>();
    fill_kernel<<<(NSLOT + 255) / 256, 256>>>();

    dim3 g1m(F_ / 64, SLOT_PAD / 128);   // 44 x 136
    gemm1_mma<<<g1m, 256>>>(x, gate_w, up_w);
    probeA_kernel<<<(PROBE_ACT + 255) / 256, 256>>>();
    dim3 g1s(F_ / SBN, SLOT_PAD / SBM);
    gemm1_simt<<<g1s, 256>>>(x, gate_w, up_w);

    dim3 g2m(D_ / 128, SLOT_PAD / 128);  // 8 x 136
    gemm2_mma<<<g2m, 256>>>(down_w);
    probeB_kernel<<<(PROBE_Y2 + 255) / 256, 256>>>();
    dim3 g2s(D_ / SBN, SLOT_PAD / SBM);
    gemm2_simt<<<g2s, 256>>>(down_w);

    combine_kernel<<<(OUT_ELEMS + 255) / 256, 256>>>(out);
}

// round 14
// speedup vs baseline: 1.2301x; 1.1753x over previous
#include <cuda_runtime.h>
#include <math.h>
#include <stdint.h>

// ---------------- problem constants ----------------
#define E_        8
#define NTOK      8192
#define D_        1024
#define F_        2816
#define NSLOT     (NTOK * 2)
#define SLOT_PAD  (NSLOT + E_ * 128)   // 17408
#define OUT_ELEMS (NTOK * D_)

#define BK   16                         // K per stage (two m16n8k8 steps)
#define NB   3                          // triple buffer, one sync/stage
#define ROWW 136                        // padded words per k-row
#define TILE_W   (BK * ROWW)            // 2176 words per tile per stage
#define SMEM_DYN (NB * TILE_W * 2 * 4)  // 52224 bytes

#define PROBE_ACT (128 * F_)
#define PROBE_Y2  (128 * D_)

// ---------------- static device scratch ----------------
__device__ __align__(128) float g_act[(size_t)SLOT_PAD * F_];
__device__ __align__(128) float g_y2[(size_t)SLOT_PAD * D_];

__device__ int   g_perm_token[SLOT_PAD];
__device__ float g_perm_w[SLOT_PAD];
__device__ int   g_tok_slot[NSLOT];
__device__ int   g_counts[E_];
__device__ int   g_cursor[E_];
__device__ int   g_pad_off[E_ + 1];
__device__ int   g_topk_idx[NSLOT];
__device__ float g_topk_w[NSLOT];
__device__ int   g_flagA;
__device__ int   g_flagB;
__device__ int   g_useMMA;

// ---------------- tf32 mma helpers ----------------
static __device__ __forceinline__ uint32_t f2tf(float v) {
    uint32_t r;
    asm("cvt.rna.tf32.f32 %0, %1;" : "=r"(r) : "f"(v));
    return r;
}
static __device__ __forceinline__ void mma_tf32(float* d, const uint32_t* a, const uint32_t* b) {
    asm volatile("mma.sync.aligned.m16n8k8.row.col.f32.tf32.tf32.f32 "
                 "{%0,%1,%2,%3}, {%4,%5,%6,%7}, {%8,%9}, {%0,%1,%2,%3};"
                 : "+f"(d[0]), "+f"(d[1]), "+f"(d[2]), "+f"(d[3])
                 : "r"(a[0]), "r"(a[1]), "r"(a[2]), "r"(a[3]), "r"(b[0]), "r"(b[1]));
}

__global__ void mma_selftest() {
    if (threadIdx.x >= 32) return;
    uint32_t one = f2tf(1.0f);
    uint32_t a[4] = {one, one, one, one};
    uint32_t b[2] = {one, one};
    float d[4] = {0.f, 0.f, 0.f, 0.f};
    mma_tf32(d, a, b);
    bool ok = (d[0] == 8.f) && (d[1] == 8.f) && (d[2] == 8.f) && (d[3] == 8.f);
    unsigned m = __ballot_sync(0xffffffffu, ok);
    if (threadIdx.x == 0) g_useMMA = (m == 0xffffffffu) ? 1 : 0;
}

// ---------------- init ----------------
__global__ void init_kernel() {
    int i = blockIdx.x * 256 + threadIdx.x;
    if (i < SLOT_PAD) { g_perm_token[i] = -1; g_perm_w[i] = 0.0f; }
    if (i < E_) g_counts[i] = 0;
    if (i == 0) { g_flagA = 0; g_flagB = 0; }
    if (i < PROBE_ACT) g_act[i] = 0.0f;
    if (i < PROBE_Y2)  g_y2[i] = 0.0f;
}

// ---------------- router / scan / fill ----------------
__global__ void router_kernel(const float* __restrict__ x, const float* __restrict__ rw) {
    int t = blockIdx.x;
    const float* xr = x + (size_t)t * D_;
    int lane = threadIdx.x & 31;
    int w    = threadIdx.x >> 5;

    double s = 0.0;
    for (int d = lane; d < D_; d += 32)
        s += (double)xr[d] * (double)rw[d * E_ + w];
    #pragma unroll
    for (int o = 16; o > 0; o >>= 1)
        s += __shfl_down_sync(0xffffffffu, s, o);

    __shared__ double sc[E_];
    if (lane == 0) sc[w] = s;
    __syncthreads();

    if (threadIdx.x == 0) {
        double m = sc[0];
        #pragma unroll
        for (int e = 1; e < E_; e++) m = fmax(m, sc[e]);
        double p[E_], sum = 0.0;
        #pragma unroll
        for (int e = 0; e < E_; e++) { p[e] = exp(sc[e] - m); sum += p[e]; }
        #pragma unroll
        for (int e = 0; e < E_; e++) p[e] /= sum;
        int i0 = 0;
        #pragma unroll
        for (int e = 1; e < E_; e++) if (p[e] > p[i0]) i0 = e;
        int i1 = (i0 == 0) ? 1 : 0;
        #pragma unroll
        for (int e = 0; e < E_; e++) { if (e == i0) continue; if (p[e] > p[i1]) i1 = e; }
        float p0 = (float)p[i0], p1 = (float)p[i1];
        float inv = 1.0f / (p0 + p1);
        g_topk_idx[t * 2 + 0] = i0;  g_topk_idx[t * 2 + 1] = i1;
        g_topk_w[t * 2 + 0] = p0 * inv;  g_topk_w[t * 2 + 1] = p1 * inv;
        atomicAdd(&g_counts[i0], 1);
        atomicAdd(&g_counts[i1], 1);
    }
}

__global__ void scan_kernel() {
    int off = 0;
    #pragma unroll
    for (int e = 0; e < E_; e++) {
        g_pad_off[e] = off;  g_cursor[e] = off;
        off += (g_counts[e] + 127) & ~127;
    }
    g_pad_off[E_] = off;
}

__global__ void fill_kernel() {
    int idx = blockIdx.x * blockDim.x + threadIdx.x;
    if (idx >= NSLOT) return;
    int e    = g_topk_idx[idx];
    int slot = atomicAdd(&g_cursor[e], 1);
    g_perm_token[slot] = idx >> 1;
    g_perm_w[slot]     = g_topk_w[idx];
    g_tok_slot[idx]    = slot;
}

// =====================================================================
// GEMM1 (tf32 mma): act = silu(x@G) * (x@U)
// R11 geometry, BK=16 (two k8 halves per stage), dynamic smem.
// CTA 128m x 64f. warps: wm=wid>>1 (32m), wn=wid&1 (32f; gate+up).
// =====================================================================
__global__ __launch_bounds__(256, 2)
void gemm1_mma(const float* __restrict__ x,
               const float* __restrict__ gate_w,
               const float* __restrict__ up_w) {
    if (!g_useMMA) return;
    int row0 = blockIdx.y * 128;
    if (row0 >= g_pad_off[E_]) return;
    int e = 0;
    while (e < E_ - 1 && g_pad_off[e + 1] <= row0) e++;
    int f0  = blockIdx.x * 64;
    int tid = threadIdx.x, wid = tid >> 5, lane = tid & 31;
    int wm = wid >> 1, wn = wid & 1;

    extern __shared__ uint32_t dyn[];
    uint32_t* AsB = dyn;                 // NB stages of A tile
    uint32_t* BsB = dyn + NB * TILE_W;   // NB stages of B tile

    // A loader (R11-style, coalesced): am = tid>>1, akq = (tid&1)*4
    int am  = tid >> 1;
    int akq = (tid & 1) * 4;
    int tok = g_perm_token[row0 + am];
    bool valid = (tok >= 0);
    const float* pa = x + (size_t)(valid ? tok : 0) * D_ + akq;

    // B loader: bkr = tid>>5 (k-rows bkr, bkr+8), bn4 = (tid&31)*4
    int bkr = tid >> 5;
    int bn4 = (tid & 31) * 4;
    const float* pb = (bn4 < 64)
        ? gate_w + ((size_t)e * D_ + bkr) * F_ + f0 + bn4
        : up_w   + ((size_t)e * D_ + bkr) * F_ + f0 + (bn4 - 64);

    float accG[2][4][4], accU[2][4][4];
    #pragma unroll
    for (int i = 0; i < 2; i++)
        #pragma unroll
        for (int j = 0; j < 4; j++)
            #pragma unroll
            for (int q = 0; q < 4; q++) { accG[i][j][q] = 0.f; accU[i][j][q] = 0.f; }

    const int NS = D_ / BK;   // 64

    float4 rA0, rA1, rB0, rB1;
    // stage 0 direct to buf0
    rA0 = valid ? *(const float4*)pa       : make_float4(0, 0, 0, 0);
    rA1 = valid ? *(const float4*)(pa + 8) : make_float4(0, 0, 0, 0);
    rB0 = *(const float4*)pb;
    rB1 = *(const float4*)(pb + (size_t)8 * F_);
    {
        float a0[4] = {rA0.x, rA0.y, rA0.z, rA0.w};
        float a1[4] = {rA1.x, rA1.y, rA1.z, rA1.w};
        #pragma unroll
        for (int q = 0; q < 4; q++) {
            AsB[(akq + q) * ROWW + am]     = f2tf(a0[q]);
            AsB[(akq + 8 + q) * ROWW + am] = f2tf(a1[q]);
        }
        uint4 b0, b1;
        b0.x = f2tf(rB0.x); b0.y = f2tf(rB0.y); b0.z = f2tf(rB0.z); b0.w = f2tf(rB0.w);
        b1.x = f2tf(rB1.x); b1.y = f2tf(rB1.y); b1.z = f2tf(rB1.z); b1.w = f2tf(rB1.w);
        *(uint4*)&BsB[bkr * ROWW + bn4]       = b0;
        *(uint4*)&BsB[(bkr + 8) * ROWW + bn4] = b1;
    }
    rA0 = valid ? *(const float4*)(pa + BK)     : make_float4(0, 0, 0, 0);
    rA1 = valid ? *(const float4*)(pa + BK + 8) : make_float4(0, 0, 0, 0);
    rB0 = *(const float4*)(pb + (size_t)BK * F_);
    rB1 = *(const float4*)(pb + (size_t)(BK + 8) * F_);
    __syncthreads();

    int lr = lane >> 2;          // 0..7
    int lk = lane & 3;           // 0..3

    #pragma unroll 1
    for (int s = 0; s < NS; s++) {
        int cb = s % NB;
        if (s + 1 < NS) {
            int nb = (s + 1) % NB;
            uint32_t* An = AsB + nb * TILE_W;
            uint32_t* Bn = BsB + nb * TILE_W;
            float a0[4] = {rA0.x, rA0.y, rA0.z, rA0.w};
            float a1[4] = {rA1.x, rA1.y, rA1.z, rA1.w};
            #pragma unroll
            for (int q = 0; q < 4; q++) {
                An[(akq + q) * ROWW + am]     = f2tf(a0[q]);
                An[(akq + 8 + q) * ROWW + am] = f2tf(a1[q]);
            }
            uint4 b0, b1;
            b0.x = f2tf(rB0.x); b0.y = f2tf(rB0.y); b0.z = f2tf(rB0.z); b0.w = f2tf(rB0.w);
            b1.x = f2tf(rB1.x); b1.y = f2tf(rB1.y); b1.z = f2tf(rB1.z); b1.w = f2tf(rB1.w);
            *(uint4*)&Bn[bkr * ROWW + bn4]       = b0;
            *(uint4*)&Bn[(bkr + 8) * ROWW + bn4] = b1;
        }
        if (s + 2 < NS) {
            int k0 = (s + 2) * BK;
            rA0 = valid ? *(const float4*)(pa + k0)     : make_float4(0, 0, 0, 0);
            rA1 = valid ? *(const float4*)(pa + k0 + 8) : make_float4(0, 0, 0, 0);
            rB0 = *(const float4*)(pb + (size_t)k0 * F_);
            rB1 = *(const float4*)(pb + (size_t)(k0 + 8) * F_);
        }
        __syncthreads();

        const uint32_t* A = AsB + cb * TILE_W;
        const uint32_t* B = BsB + cb * TILE_W;
        #pragma unroll
        for (int h = 0; h < 2; h++) {
            int kb = 8 * h;
            uint32_t a[2][4];
            #pragma unroll
            for (int i = 0; i < 2; i++) {
                int m0 = 32 * wm + 16 * i + lr;
                a[i][0] = A[(kb + lk) * ROWW + m0];
                a[i][1] = A[(kb + lk) * ROWW + m0 + 8];
                a[i][2] = A[(kb + lk + 4) * ROWW + m0];
                a[i][3] = A[(kb + lk + 4) * ROWW + m0 + 8];
            }
            #pragma unroll
            for (int j = 0; j < 4; j++) {
                int ng = 32 * wn + 8 * j + lr;
                uint32_t bg[2], bu[2];
                bg[0] = B[(kb + lk) * ROWW + ng];
                bg[1] = B[(kb + lk + 4) * ROWW + ng];
                bu[0] = B[(kb + lk) * ROWW + ng + 64];
                bu[1] = B[(kb + lk + 4) * ROWW + ng + 64];
                #pragma unroll
                for (int i = 0; i < 2; i++) {
                    mma_tf32(accG[i][j], a[i], bg);
                    mma_tf32(accU[i][j], a[i], bu);
                }
            }
        }
    }

    // epilogue: SwiGLU, fp32 act
    #pragma unroll
    for (int i = 0; i < 2; i++)
        #pragma unroll
        for (int j = 0; j < 4; j++) {
            int fb = f0 + 32 * wn + 8 * j + 2 * (lane & 3);
            #pragma unroll
            for (int h = 0; h < 2; h++) {
                int row = row0 + 32 * wm + 16 * i + (lane >> 2) + 8 * h;
                float g0 = accG[i][j][2 * h + 0], g1 = accG[i][j][2 * h + 1];
                float u0 = accU[i][j][2 * h + 0], u1 = accU[i][j][2 * h + 1];
                float2 o;
                o.x = (g0 / (1.0f + __expf(-g0))) * u0;
                o.y = (g1 / (1.0f + __expf(-g1))) * u1;
                *(float2*)(g_act + (size_t)row * F_ + fb) = o;
            }
        }
}

// =====================================================================
// GEMM2 (tf32 mma): y2 = w * (act @ Wdown) -- BK=16, dynamic smem
// CTA 128m x 128n. warps: wm=wid>>1 (32m), wn=wid&1 (64n).
// =====================================================================
__global__ __launch_bounds__(256, 2)
void gemm2_mma(const float* __restrict__ down_w) {
    if (!g_useMMA) return;
    int row0 = blockIdx.y * 128;
    if (row0 >= g_pad_off[E_]) return;
    int e = 0;
    while (e < E_ - 1 && g_pad_off[e + 1] <= row0) e++;
    int n0  = blockIdx.x * 128;
    int tid = threadIdx.x, wid = tid >> 5, lane = tid & 31;
    int wm = wid >> 1, wn = wid & 1;

    extern __shared__ uint32_t dyn[];
    uint32_t* AsB = dyn;
    uint32_t* BsB = dyn + NB * TILE_W;

    int am  = tid >> 1;
    int akq = (tid & 1) * 4;
    const float* pa = g_act + (size_t)(row0 + am) * F_ + akq;

    int bkr = tid >> 5;
    int bn4 = (tid & 31) * 4;
    const float* pb = down_w + ((size_t)e * F_ + bkr) * D_ + n0 + bn4;

    float acc[2][8][4];
    #pragma unroll
    for (int i = 0; i < 2; i++)
        #pragma unroll
        for (int j = 0; j < 8; j++)
            #pragma unroll
            for (int q = 0; q < 4; q++) acc[i][j][q] = 0.f;

    const int NS = F_ / BK;   // 176

    float4 rA0, rA1, rB0, rB1;
    rA0 = *(const float4*)pa;
    rA1 = *(const float4*)(pa + 8);
    rB0 = *(const float4*)pb;
    rB1 = *(const float4*)(pb + (size_t)8 * D_);
    {
        float a0[4] = {rA0.x, rA0.y, rA0.z, rA0.w};
        float a1[4] = {rA1.x, rA1.y, rA1.z, rA1.w};
        #pragma unroll
        for (int q = 0; q < 4; q++) {
            AsB[(akq + q) * ROWW + am]     = f2tf(a0[q]);
            AsB[(akq + 8 + q) * ROWW + am] = f2tf(a1[q]);
        }
        uint4 b0, b1;
        b0.x = f2tf(rB0.x); b0.y = f2tf(rB0.y); b0.z = f2tf(rB0.z); b0.w = f2tf(rB0.w);
        b1.x = f2tf(rB1.x); b1.y = f2tf(rB1.y); b1.z = f2tf(rB1.z); b1.w = f2tf(rB1.w);
        *(uint4*)&BsB[bkr * ROWW + bn4]       = b0;
        *(uint4*)&BsB[(bkr + 8) * ROWW + bn4] = b1;
    }
    rA0 = *(const float4*)(pa + BK);
    rA1 = *(const float4*)(pa + BK + 8);
    rB0 = *(const float4*)(pb + (size_t)BK * D_);
    rB1 = *(const float4*)(pb + (size_t)(BK + 8) * D_);
    __syncthreads();

    int lr = lane >> 2;
    int lk = lane & 3;

    #pragma unroll 1
    for (int s = 0; s < NS; s++) {
        int cb = s % NB;
        if (s + 1 < NS) {
            int nb = (s + 1) % NB;
            uint32_t* An = AsB + nb * TILE_W;
            uint32_t* Bn = BsB + nb * TILE_W;
            float a0[4] = {rA0.x, rA0.y, rA0.z, rA0.w};
            float a1[4] = {rA1.x, rA1.y, rA1.z, rA1.w};
            #pragma unroll
            for (int q = 0; q < 4; q++) {
                An[(akq + q) * ROWW + am]     = f2tf(a0[q]);
                An[(akq + 8 + q) * ROWW + am] = f2tf(a1[q]);
            }
            uint4 b0, b1;
            b0.x = f2tf(rB0.x); b0.y = f2tf(rB0.y); b0.z = f2tf(rB0.z); b0.w = f2tf(rB0.w);
            b1.x = f2tf(rB1.x); b1.y = f2tf(rB1.y); b1.z = f2tf(rB1.z); b1.w = f2tf(rB1.w);
            *(uint4*)&Bn[bkr * ROWW + bn4]       = b0;
            *(uint4*)&Bn[(bkr + 8) * ROWW + bn4] = b1;
        }
        if (s + 2 < NS) {
            int k0 = (s + 2) * BK;
            rA0 = *(const float4*)(pa + k0);
            rA1 = *(const float4*)(pa + k0 + 8);
            rB0 = *(const float4*)(pb + (size_t)k0 * D_);
            rB1 = *(const float4*)(pb + (size_t)(k0 + 8) * D_);
        }
        __syncthreads();

        const uint32_t* A = AsB + cb * TILE_W;
        const uint32_t* B = BsB + cb * TILE_W;
        #pragma unroll
        for (int h = 0; h < 2; h++) {
            int kb = 8 * h;
            uint32_t a[2][4];
            #pragma unroll
            for (int i = 0; i < 2; i++) {
                int m0 = 32 * wm + 16 * i + lr;
                a[i][0] = A[(kb + lk) * ROWW + m0];
                a[i][1] = A[(kb + lk) * ROWW + m0 + 8];
                a[i][2] = A[(kb + lk + 4) * ROWW + m0];
                a[i][3] = A[(kb + lk + 4) * ROWW + m0 + 8];
            }
            #pragma unroll
            for (int j = 0; j < 8; j++) {
                int nn = 64 * wn + 8 * j + lr;
                uint32_t b[2];
                b[0] = B[(kb + lk) * ROWW + nn];
                b[1] = B[(kb + lk + 4) * ROWW + nn];
                #pragma unroll
                for (int i = 0; i < 2; i++)
                    mma_tf32(acc[i][j], a[i], b);
            }
        }
    }

    #pragma unroll
    for (int i = 0; i < 2; i++)
        #pragma unroll
        for (int h = 0; h < 2; h++) {
            int row = row0 + 32 * wm + 16 * i + (lane >> 2) + 8 * h;
            float w = g_perm_w[row];
            #pragma unroll
            for (int j = 0; j < 8; j++) {
                int nn = n0 + 64 * wn + 8 * j + 2 * (lane & 3);
                float2 v;
                v.x = acc[i][j][2 * h + 0] * w;
                v.y = acc[i][j][2 * h + 1] * w;
                *(float2*)(g_y2 + (size_t)row * D_ + nn) = v;
            }
        }
}

// ---------------- probes ----------------
__global__ void probeA_kernel() {
    int i = blockIdx.x * 256 + threadIdx.x;
    if (i >= PROBE_ACT) return;
    if (((const uint32_t*)g_act)[i] != 0) g_flagA = 1;
}
__global__ void probeB_kernel() {
    int i = blockIdx.x * 256 + threadIdx.x;
    if (i >= PROBE_Y2) return;
    if (((const uint32_t*)g_y2)[i] != 0) g_flagB = 1;
}

// ---------------- SIMT fallbacks (fp32 insurance) ----------------
#define SBM 64
#define SBN 64
#define SBK 16

__global__ __launch_bounds__(256)
void gemm1_simt(const float* __restrict__ x,
                const float* __restrict__ gate_w,
                const float* __restrict__ up_w) {
    if (g_flagA) return;
    int row0 = blockIdx.y * SBM;
    if (row0 >= g_pad_off[E_]) return;
    int e = 0;
    while (e < E_ - 1 && g_pad_off[e + 1] <= row0) e++;
    const float* G = gate_w + (size_t)e * D_ * F_;
    const float* U = up_w   + (size_t)e * D_ * F_;
    int n0 = blockIdx.x * SBN;

    __shared__ float As2[SBK][SBM + 4];
    __shared__ float Bg[SBK][SBN];
    __shared__ float Bu[SBK][SBN];

    int tid   = threadIdx.x;
    int a_row = tid >> 2;
    int a_k   = (tid & 3) * 4;
    int tok   = g_perm_token[row0 + a_row];
    bool valid = (tok >= 0);
    const float* xrow = x + (size_t)(valid ? tok : 0) * D_;

    int b_k = tid >> 4;
    int b_n = (tid & 15) * 4;
    int ty = tid >> 4, tx = tid & 15;

    float ag[4][4] = {}, au[4][4] = {};

    for (int k0 = 0; k0 < D_; k0 += SBK) {
        float4 av = valid ? *(const float4*)(xrow + k0 + a_k)
                          : make_float4(0.f, 0.f, 0.f, 0.f);
        As2[a_k + 0][a_row] = av.x;  As2[a_k + 1][a_row] = av.y;
        As2[a_k + 2][a_row] = av.z;  As2[a_k + 3][a_row] = av.w;
        *(float4*)&Bg[b_k][b_n] = *(const float4*)(G + (size_t)(k0 + b_k) * F_ + n0 + b_n);
        *(float4*)&Bu[b_k][b_n] = *(const float4*)(U + (size_t)(k0 + b_k) * F_ + n0 + b_n);
        __syncthreads();
        #pragma unroll
        for (int kk = 0; kk < SBK; kk++) {
            float4 a4 = *(const float4*)&As2[kk][ty * 4];
            float4 g4 = *(const float4*)&Bg[kk][tx * 4];
            float4 u4 = *(const float4*)&Bu[kk][tx * 4];
            float am[4] = {a4.x, a4.y, a4.z, a4.w};
            float gm[4] = {g4.x, g4.y, g4.z, g4.w};
            float um[4] = {u4.x, u4.y, u4.z, u4.w};
            #pragma unroll
            for (int i = 0; i < 4; i++)
                #pragma unroll
                for (int j = 0; j < 4; j++) {
                    ag[i][j] += am[i] * gm[j];
                    au[i][j] += am[i] * um[j];
                }
        }
        __syncthreads();
    }

    #pragma unroll
    for (int i = 0; i < 4; i++) {
        int r = row0 + ty * 4 + i;
        size_t base = (size_t)r * F_ + n0 + tx * 4;
        #pragma unroll
        for (int j = 0; j < 4; j++) {
            float g = ag[i][j], u = au[i][j];
            g_act[base + j] = (g / (1.0f + __expf(-g))) * u;
        }
    }
}

__global__ __launch_bounds__(256)
void gemm2_simt(const float* __restrict__ down_w) {
    if (g_flagB) return;
    int row0 = blockIdx.y * SBM;
    if (row0 >= g_pad_off[E_]) return;
    int e = 0;
    while (e < E_ - 1 && g_pad_off[e + 1] <= row0) e++;
    const float* Wd = down_w + (size_t)e * F_ * D_;
    int n0 = blockIdx.x * SBN;

    __shared__ float As2[SBK][SBM + 4];
    __shared__ float Bs2[SBK][SBN];

    int tid   = threadIdx.x;
    int a_row = tid >> 2;
    int a_k   = (tid & 3) * 4;
    size_t abase = (size_t)(row0 + a_row) * F_;

    int b_k = tid >> 4;
    int b_n = (tid & 15) * 4;
    int ty = tid >> 4, tx = tid & 15;

    float acc[4][4] = {};

    for (int k0 = 0; k0 < F_; k0 += SBK) {
        float4 av = *(const float4*)(g_act + abase + k0 + a_k);
        As2[a_k + 0][a_row] = av.x;  As2[a_k + 1][a_row] = av.y;
        As2[a_k + 2][a_row] = av.z;  As2[a_k + 3][a_row] = av.w;
        *(float4*)&Bs2[b_k][b_n] = *(const float4*)(Wd + (size_t)(k0 + b_k) * D_ + n0 + b_n);
        __syncthreads();
        #pragma unroll
        for (int kk = 0; kk < SBK; kk++) {
            float4 a4 = *(const float4*)&As2[kk][ty * 4];
            float4 b4 = *(const float4*)&Bs2[kk][tx * 4];
            float am[4] = {a4.x, a4.y, a4.z, a4.w};
            float bm[4] = {b4.x, b4.y, b4.z, b4.w};
            #pragma unroll
            for (int i = 0; i < 4; i++)
                #pragma unroll
                for (int j = 0; j < 4; j++)
                    acc[i][j] += am[i] * bm[j];
        }
        __syncthreads();
    }

    #pragma unroll
    for (int i = 0; i < 4; i++) {
        int r = row0 + ty * 4 + i;
        float w = g_perm_w[r];
        float* yrow = g_y2 + (size_t)r * D_ + n0 + tx * 4;
        #pragma unroll
        for (int j = 0; j < 4; j++)
            yrow[j] = acc[i][j] * w;
    }
}

// ---------------- combine ----------------
__global__ void combine_kernel(float* __restrict__ out) {
    int i = blockIdx.x * 256 + threadIdx.x;
    if (i >= OUT_ELEMS) return;
    int t = i >> 10, d = i & 1023;
    int s0 = g_tok_slot[t * 2 + 0];
    int s1 = g_tok_slot[t * 2 + 1];
    out[i] = g_y2[(size_t)s0 * D_ + d] + g_y2[(size_t)s1 * D_ + d];
}

// ---------------- launch ----------------
extern "C" void kernel_launch(void* const* d_in, const int* in_sizes, int n_in,
                              void* d_out, int out_size) {
    const float* x      = (const float*)d_in[0];
    const float* rw     = (const float*)d_in[1];
    const float* gate_w = (const float*)d_in[2];
    const float* up_w   = (const float*)d_in[3];
    const float* down_w = (const float*)d_in[4];
    float* out = (float*)d_out;

    static int smem_set = 0;
    if (!smem_set) {
        cudaFuncSetAttribute(gemm1_mma, cudaFuncAttributeMaxDynamicSharedMemorySize, SMEM_DYN);
        cudaFuncSetAttribute(gemm2_mma, cudaFuncAttributeMaxDynamicSharedMemorySize, SMEM_DYN);
        smem_set = 1;
    }

    mma_selftest<<<1, 32>>>();
    init_kernel<<<(PROBE_ACT + 255) / 256, 256>>>();
    router_kernel<<<NTOK, 256>>>(x, rw);
    scan_kernel<<<1, 1>>>();
    fill_kernel<<<(NSLOT + 255) / 256, 256>>>();

    dim3 g1m(F_ / 64, SLOT_PAD / 128);   // 44 x 136
    gemm1_mma<<<g1m, 256, SMEM_DYN>>>(x, gate_w, up_w);
    probeA_kernel<<<(PROBE_ACT + 255) / 256, 256>>>();
    dim3 g1s(F_ / SBN, SLOT_PAD / SBM);
    gemm1_simt<<<g1s, 256>>>(x, gate_w, up_w);

    dim3 g2m(D_ / 128, SLOT_PAD / 128);  // 8 x 136
    gemm2_mma<<<g2m, 256, SMEM_DYN>>>(down_w);
    probeB_kernel<<<(PROBE_Y2 + 255) / 256, 256>>>();
    dim3 g2s(D_ / SBN, SLOT_PAD / SBM);
    gemm2_simt<<<g2s, 256>>>(down_w);

    combine_kernel<<<(OUT_ELEMS + 255) / 256, 256>>>(out);
}

// round 15
// speedup vs baseline: 1.2689x; 1.0315x over previous
#include <cuda_runtime.h>
#include <math.h>
#include <stdint.h>

// ---------------- problem constants ----------------
#define E_        8
#define NTOK      8192
#define D_        1024
#define F_        2816
#define NSLOT     (NTOK * 2)
#define SLOT_PAD  (NSLOT + E_ * 128)   // 17408
#define OUT_ELEMS (NTOK * D_)

#define BK    16                        // K per stage (two m16n8k8 halves)
#define NB    3                         // triple buffer, one sync/stage
#define ASTG  2112                      // 16 groups x 132 words
#define BSTG  2112                      // 32 blocks x 66 words
#define STGW  (ASTG + BSTG)             // 4224 words per stage
#define SMEM_DYN (NB * STGW * 4)        // 50688 bytes

#define PROBE_ACT (128 * F_)
#define PROBE_Y2  (128 * D_)

// ---------------- static device scratch ----------------
__device__ __align__(128) float g_act[(size_t)SLOT_PAD * F_];
__device__ __align__(128) float g_y2[(size_t)SLOT_PAD * D_];

__device__ int   g_perm_token[SLOT_PAD];
__device__ float g_perm_w[SLOT_PAD];
__device__ int   g_tok_slot[NSLOT];
__device__ int   g_counts[E_];
__device__ int   g_cursor[E_];
__device__ int   g_pad_off[E_ + 1];
__device__ int   g_topk_idx[NSLOT];
__device__ float g_topk_w[NSLOT];
__device__ int   g_flagA;
__device__ int   g_flagB;
__device__ int   g_useMMA;

// ---------------- tf32 mma helpers ----------------
static __device__ __forceinline__ uint32_t f2tf(float v) {
    uint32_t r;
    asm("cvt.rna.tf32.f32 %0, %1;" : "=r"(r) : "f"(v));
    return r;
}
static __device__ __forceinline__ void mma_tf32(float* d, const uint32_t* a, const uint32_t* b) {
    asm volatile("mma.sync.aligned.m16n8k8.row.col.f32.tf32.tf32.f32 "
                 "{%0,%1,%2,%3}, {%4,%5,%6,%7}, {%8,%9}, {%0,%1,%2,%3};"
                 : "+f"(d[0]), "+f"(d[1]), "+f"(d[2]), "+f"(d[3])
                 : "r"(a[0]), "r"(a[1]), "r"(a[2]), "r"(a[3]), "r"(b[0]), "r"(b[1]));
}

__global__ void mma_selftest() {
    if (threadIdx.x >= 32) return;
    uint32_t one = f2tf(1.0f);
    uint32_t a[4] = {one, one, one, one};
    uint32_t b[2] = {one, one};
    float d[4] = {0.f, 0.f, 0.f, 0.f};
    mma_tf32(d, a, b);
    bool ok = (d[0] == 8.f) && (d[1] == 8.f) && (d[2] == 8.f) && (d[3] == 8.f);
    unsigned m = __ballot_sync(0xffffffffu, ok);
    if (threadIdx.x == 0) g_useMMA = (m == 0xffffffffu) ? 1 : 0;
}

// ---------------- init ----------------
__global__ void init_kernel() {
    int i = blockIdx.x * 256 + threadIdx.x;
    if (i < SLOT_PAD) { g_perm_token[i] = -1; g_perm_w[i] = 0.0f; }
    if (i < E_) g_counts[i] = 0;
    if (i == 0) { g_flagA = 0; g_flagB = 0; }
    if (i < PROBE_ACT) g_act[i] = 0.0f;
    if (i < PROBE_Y2)  g_y2[i] = 0.0f;
}

// ---------------- router / scan / fill ----------------
__global__ void router_kernel(const float* __restrict__ x, const float* __restrict__ rw) {
    int t = blockIdx.x;
    const float* xr = x + (size_t)t * D_;
    int lane = threadIdx.x & 31;
    int w    = threadIdx.x >> 5;

    double s = 0.0;
    for (int d = lane; d < D_; d += 32)
        s += (double)xr[d] * (double)rw[d * E_ + w];
    #pragma unroll
    for (int o = 16; o > 0; o >>= 1)
        s += __shfl_down_sync(0xffffffffu, s, o);

    __shared__ double sc[E_];
    if (lane == 0) sc[w] = s;
    __syncthreads();

    if (threadIdx.x == 0) {
        double m = sc[0];
        #pragma unroll
        for (int e = 1; e < E_; e++) m = fmax(m, sc[e]);
        double p[E_], sum = 0.0;
        #pragma unroll
        for (int e = 0; e < E_; e++) { p[e] = exp(sc[e] - m); sum += p[e]; }
        #pragma unroll
        for (int e = 0; e < E_; e++) p[e] /= sum;
        int i0 = 0;
        #pragma unroll
        for (int e = 1; e < E_; e++) if (p[e] > p[i0]) i0 = e;
        int i1 = (i0 == 0) ? 1 : 0;
        #pragma unroll
        for (int e = 0; e < E_; e++) { if (e == i0) continue; if (p[e] > p[i1]) i1 = e; }
        float p0 = (float)p[i0], p1 = (float)p[i1];
        float inv = 1.0f / (p0 + p1);
        g_topk_idx[t * 2 + 0] = i0;  g_topk_idx[t * 2 + 1] = i1;
        g_topk_w[t * 2 + 0] = p0 * inv;  g_topk_w[t * 2 + 1] = p1 * inv;
        atomicAdd(&g_counts[i0], 1);
        atomicAdd(&g_counts[i1], 1);
    }
}

__global__ void scan_kernel() {
    int off = 0;
    #pragma unroll
    for (int e = 0; e < E_; e++) {
        g_pad_off[e] = off;  g_cursor[e] = off;
        off += (g_counts[e] + 127) & ~127;
    }
    g_pad_off[E_] = off;
}

__global__ void fill_kernel() {
    int idx = blockIdx.x * blockDim.x + threadIdx.x;
    if (idx >= NSLOT) return;
    int e    = g_topk_idx[idx];
    int slot = atomicAdd(&g_cursor[e], 1);
    g_perm_token[slot] = idx >> 1;
    g_perm_w[slot]     = g_topk_w[idx];
    g_tok_slot[idx]    = slot;
}

// ---------------- fragment-layout store helpers ----------------
// A value (m, k): group = (k>>3)*8 + (m>>4); lane = 4*(m&7) + (k&3);
//                line = lane ^ (lane>>3); q = ((m>>3)&1) + 2*((k>>2)&1)
// word addr = group*132 + line*4 + q
static __device__ __forceinline__ void store_a8(uint32_t* An, int am, int akq,
                                                const float* a0, const float* a1) {
    int lrA = am & 7;
    int qA  = ((am >> 3) & 1) + 2 * (akq >> 2);
    int g0  = (am >> 4) * 132;
    #pragma unroll
    for (int j = 0; j < 4; j++) {
        int lane = 4 * lrA + j;
        int line = lane ^ (lane >> 3);
        An[g0 + line * 4 + qA]            = f2tf(a0[j]);
        An[8 * 132 + g0 + line * 4 + qA]  = f2tf(a1[j]);
    }
}
// B value (k, ns): block = (k>>3)*16 + (ns>>3); lane = 4*(ns&7) + (k&3);
//                  c = (k>>2)&1;  word addr = block*66 + 2*lane + c
static __device__ __forceinline__ void store_b8(uint32_t* Bn, int bkr, int bn4,
                                                const float* b0, const float* b1) {
    int klow = bkr & 3;
    int cB   = bkr >> 2;
    #pragma unroll
    for (int t = 0; t < 4; t++) {
        int ns   = bn4 + t;
        int lane = 4 * (ns & 7) + klow;
        int blk  = (ns >> 3) * 66;
        Bn[blk + 2 * lane + cB]            = f2tf(b0[t]);
        Bn[16 * 66 + blk + 2 * lane + cB]  = f2tf(b1[t]);
    }
}

// =====================================================================
// GEMM1 (tf32 mma, fragment layout): act = silu(x@G) * (x@U)
// CTA 128m x 64f (gate+up). warps: wm=wid>>1 (32m), wn=wid&1 (32f).
// =====================================================================
__global__ __launch_bounds__(256, 2)
void gemm1_mma(const float* __restrict__ x,
               const float* __restrict__ gate_w,
               const float* __restrict__ up_w) {
    if (!g_useMMA) return;
    int row0 = blockIdx.y * 128;
    if (row0 >= g_pad_off[E_]) return;
    int e = 0;
    while (e < E_ - 1 && g_pad_off[e + 1] <= row0) e++;
    int f0  = blockIdx.x * 64;
    int tid = threadIdx.x, wid = tid >> 5, lane = tid & 31;
    int wm = wid >> 1, wn = wid & 1;

    extern __shared__ uint32_t dyn[];

    // A loader (coalesced): am = tid>>1, akq = (tid&1)*4
    int am  = tid >> 1;
    int akq = (tid & 1) * 4;
    int tok = g_perm_token[row0 + am];
    bool valid = (tok >= 0);
    const float* pa = x + (size_t)(valid ? tok : 0) * D_ + akq;

    // B loader: bkr = tid>>5 (k rows bkr, bkr+8), bn4 = (tid&31)*4
    int bkr = tid >> 5;
    int bn4 = (tid & 31) * 4;
    const float* pb = (bn4 < 64)
        ? gate_w + ((size_t)e * D_ + bkr) * F_ + f0 + bn4
        : up_w   + ((size_t)e * D_ + bkr) * F_ + f0 + (bn4 - 64);

    float accG[2][4][4], accU[2][4][4];
    #pragma unroll
    for (int i = 0; i < 2; i++)
        #pragma unroll
        for (int j = 0; j < 4; j++)
            #pragma unroll
            for (int q = 0; q < 4; q++) { accG[i][j][q] = 0.f; accU[i][j][q] = 0.f; }

    const int NS = D_ / BK;   // 64

    float4 rA0, rA1, rB0, rB1;
    rA0 = valid ? *(const float4*)pa       : make_float4(0, 0, 0, 0);
    rA1 = valid ? *(const float4*)(pa + 8) : make_float4(0, 0, 0, 0);
    rB0 = *(const float4*)pb;
    rB1 = *(const float4*)(pb + (size_t)8 * F_);
    store_a8(dyn, am, akq, (const float*)&rA0, (const float*)&rA1);
    store_b8(dyn + ASTG, bkr, bn4, (const float*)&rB0, (const float*)&rB1);
    rA0 = valid ? *(const float4*)(pa + BK)     : make_float4(0, 0, 0, 0);
    rA1 = valid ? *(const float4*)(pa + BK + 8) : make_float4(0, 0, 0, 0);
    rB0 = *(const float4*)(pb + (size_t)BK * F_);
    rB1 = *(const float4*)(pb + (size_t)(BK + 8) * F_);
    __syncthreads();

    int lineoff = (lane ^ (lane >> 3)) * 4;   // A consumer word offset
    int boff    = 2 * lane;                   // B consumer word offset

    #pragma unroll 1
    for (int s = 0; s < NS; s++) {
        int cb = s % NB;
        if (s + 1 < NS) {
            uint32_t* stg = dyn + ((s + 1) % NB) * STGW;
            store_a8(stg, am, akq, (const float*)&rA0, (const float*)&rA1);
            store_b8(stg + ASTG, bkr, bn4, (const float*)&rB0, (const float*)&rB1);
        }
        if (s + 2 < NS) {
            int k0 = (s + 2) * BK;
            rA0 = valid ? *(const float4*)(pa + k0)     : make_float4(0, 0, 0, 0);
            rA1 = valid ? *(const float4*)(pa + k0 + 8) : make_float4(0, 0, 0, 0);
            rB0 = *(const float4*)(pb + (size_t)k0 * F_);
            rB1 = *(const float4*)(pb + (size_t)(k0 + 8) * F_);
        }
        __syncthreads();

        const uint32_t* A = dyn + cb * STGW;
        const uint32_t* B = A + ASTG;
        #pragma unroll
        for (int h = 0; h < 2; h++) {
            uint4 af[2];
            #pragma unroll
            for (int i = 0; i < 2; i++)
                af[i] = *(const uint4*)&A[(h * 8 + 2 * wm + i) * 132 + lineoff];
            #pragma unroll
            for (int j = 0; j < 4; j++) {
                uint2 bgv = *(const uint2*)&B[(h * 16 + 4 * wn + j) * 66 + boff];
                uint2 buv = *(const uint2*)&B[(h * 16 + 8 + 4 * wn + j) * 66 + boff];
                #pragma unroll
                for (int i = 0; i < 2; i++) {
                    mma_tf32(accG[i][j], (const uint32_t*)&af[i], (const uint32_t*)&bgv);
                    mma_tf32(accU[i][j], (const uint32_t*)&af[i], (const uint32_t*)&buv);
                }
            }
        }
    }

    // epilogue: SwiGLU, fp32 act
    #pragma unroll
    for (int i = 0; i < 2; i++)
        #pragma unroll
        for (int j = 0; j < 4; j++) {
            int fb = f0 + 32 * wn + 8 * j + 2 * (lane & 3);
            #pragma unroll
            for (int h = 0; h < 2; h++) {
                int row = row0 + 32 * wm + 16 * i + (lane >> 2) + 8 * h;
                float g0 = accG[i][j][2 * h + 0], g1 = accG[i][j][2 * h + 1];
                float u0 = accU[i][j][2 * h + 0], u1 = accU[i][j][2 * h + 1];
                float2 o;
                o.x = (g0 / (1.0f + __expf(-g0))) * u0;
                o.y = (g1 / (1.0f + __expf(-g1))) * u1;
                *(float2*)(g_act + (size_t)row * F_ + fb) = o;
            }
        }
}

// =====================================================================
// GEMM2 (tf32 mma, fragment layout): y2 = w * (act @ Wdown)
// CTA 128m x 128n. warps: wm=wid>>1 (32m), wn=wid&1 (64n).
// =====================================================================
__global__ __launch_bounds__(256, 2)
void gemm2_mma(const float* __restrict__ down_w) {
    if (!g_useMMA) return;
    int row0 = blockIdx.y * 128;
    if (row0 >= g_pad_off[E_]) return;
    int e = 0;
    while (e < E_ - 1 && g_pad_off[e + 1] <= row0) e++;
    int n0  = blockIdx.x * 128;
    int tid = threadIdx.x, wid = tid >> 5, lane = tid & 31;
    int wm = wid >> 1, wn = wid & 1;

    extern __shared__ uint32_t dyn[];

    int am  = tid >> 1;
    int akq = (tid & 1) * 4;
    const float* pa = g_act + (size_t)(row0 + am) * F_ + akq;

    int bkr = tid >> 5;
    int bn4 = (tid & 31) * 4;
    const float* pb = down_w + ((size_t)e * F_ + bkr) * D_ + n0 + bn4;

    float acc[2][8][4];
    #pragma unroll
    for (int i = 0; i < 2; i++)
        #pragma unroll
        for (int j = 0; j < 8; j++)
            #pragma unroll
            for (int q = 0; q < 4; q++) acc[i][j][q] = 0.f;

    const int NS = F_ / BK;   // 176

    float4 rA0, rA1, rB0, rB1;
    rA0 = *(const float4*)pa;
    rA1 = *(const float4*)(pa + 8);
    rB0 = *(const float4*)pb;
    rB1 = *(const float4*)(pb + (size_t)8 * D_);
    store_a8(dyn, am, akq, (const float*)&rA0, (const float*)&rA1);
    store_b8(dyn + ASTG, bkr, bn4, (const float*)&rB0, (const float*)&rB1);
    rA0 = *(const float4*)(pa + BK);
    rA1 = *(const float4*)(pa + BK + 8);
    rB0 = *(const float4*)(pb + (size_t)BK * D_);
    rB1 = *(const float4*)(pb + (size_t)(BK + 8) * D_);
    __syncthreads();

    int lineoff = (lane ^ (lane >> 3)) * 4;
    int boff    = 2 * lane;

    #pragma unroll 1
    for (int s = 0; s < NS; s++) {
        int cb = s % NB;
        if (s + 1 < NS) {
            uint32_t* stg = dyn + ((s + 1) % NB) * STGW;
            store_a8(stg, am, akq, (const float*)&rA0, (const float*)&rA1);
            store_b8(stg + ASTG, bkr, bn4, (const float*)&rB0, (const float*)&rB1);
        }
        if (s + 2 < NS) {
            int k0 = (s + 2) * BK;
            rA0 = *(const float4*)(pa + k0);
            rA1 = *(const float4*)(pa + k0 + 8);
            rB0 = *(const float4*)(pb + (size_t)k0 * D_);
            rB1 = *(const float4*)(pb + (size_t)(k0 + 8) * D_);
        }
        __syncthreads();

        const uint32_t* A = dyn + cb * STGW;
        const uint32_t* B = A + ASTG;
        #pragma unroll
        for (int h = 0; h < 2; h++) {
            uint4 af[2];
            #pragma unroll
            for (int i = 0; i < 2; i++)
                af[i] = *(const uint4*)&A[(h * 8 + 2 * wm + i) * 132 + lineoff];
            #pragma unroll
            for (int j = 0; j < 8; j++) {
                uint2 bv = *(const uint2*)&B[(h * 16 + 8 * wn + j) * 66 + boff];
                #pragma unroll
                for (int i = 0; i < 2; i++)
                    mma_tf32(acc[i][j], (const uint32_t*)&af[i], (const uint32_t*)&bv);
            }
        }
    }

    #pragma unroll
    for (int i = 0; i < 2; i++)
        #pragma unroll
        for (int h = 0; h < 2; h++) {
            int row = row0 + 32 * wm + 16 * i + (lane >> 2) + 8 * h;
            float w = g_perm_w[row];
            #pragma unroll
            for (int j = 0; j < 8; j++) {
                int nn = n0 + 64 * wn + 8 * j + 2 * (lane & 3);
                float2 v;
                v.x = acc[i][j][2 * h + 0] * w;
                v.y = acc[i][j][2 * h + 1] * w;
                *(float2*)(g_y2 + (size_t)row * D_ + nn) = v;
            }
        }
}

// ---------------- probes ----------------
__global__ void probeA_kernel() {
    int i = blockIdx.x * 256 + threadIdx.x;
    if (i >= PROBE_ACT) return;
    if (((const uint32_t*)g_act)[i] != 0) g_flagA = 1;
}
__global__ void probeB_kernel() {
    int i = blockIdx.x * 256 + threadIdx.x;
    if (i >= PROBE_Y2) return;
    if (((const uint32_t*)g_y2)[i] != 0) g_flagB = 1;
}

// ---------------- SIMT fallbacks (fp32 insurance) ----------------
#define SBM 64
#define SBN 64
#define SBK 16

__global__ __launch_bounds__(256)
void gemm1_simt(const float* __restrict__ x,
                const float* __restrict__ gate_w,
                const float* __restrict__ up_w) {
    if (g_flagA) return;
    int row0 = blockIdx.y * SBM;
    if (row0 >= g_pad_off[E_]) return;
    int e = 0;
    while (e < E_ - 1 && g_pad_off[e + 1] <= row0) e++;
    const float* G = gate_w + (size_t)e * D_ * F_;
    const float* U = up_w   + (size_t)e * D_ * F_;
    int n0 = blockIdx.x * SBN;

    __shared__ float As2[SBK][SBM + 4];
    __shared__ float Bg[SBK][SBN];
    __shared__ float Bu[SBK][SBN];

    int tid   = threadIdx.x;
    int a_row = tid >> 2;
    int a_k   = (tid & 3) * 4;
    int tok   = g_perm_token[row0 + a_row];
    bool valid = (tok >= 0);
    const float* xrow = x + (size_t)(valid ? tok : 0) * D_;

    int b_k = tid >> 4;
    int b_n = (tid & 15) * 4;
    int ty = tid >> 4, tx = tid & 15;

    float ag[4][4] = {}, au[4][4] = {};

    for (int k0 = 0; k0 < D_; k0 += SBK) {
        float4 av = valid ? *(const float4*)(xrow + k0 + a_k)
                          : make_float4(0.f, 0.f, 0.f, 0.f);
        As2[a_k + 0][a_row] = av.x;  As2[a_k + 1][a_row] = av.y;
        As2[a_k + 2][a_row] = av.z;  As2[a_k + 3][a_row] = av.w;
        *(float4*)&Bg[b_k][b_n] = *(const float4*)(G + (size_t)(k0 + b_k) * F_ + n0 + b_n);
        *(float4*)&Bu[b_k][b_n] = *(const float4*)(U + (size_t)(k0 + b_k) * F_ + n0 + b_n);
        __syncthreads();
        #pragma unroll
        for (int kk = 0; kk < SBK; kk++) {
            float4 a4 = *(const float4*)&As2[kk][ty * 4];
            float4 g4 = *(const float4*)&Bg[kk][tx * 4];
            float4 u4 = *(const float4*)&Bu[kk][tx * 4];
            float am[4] = {a4.x, a4.y, a4.z, a4.w};
            float gm[4] = {g4.x, g4.y, g4.z, g4.w};
            float um[4] = {u4.x, u4.y, u4.z, u4.w};
            #pragma unroll
            for (int i = 0; i < 4; i++)
                #pragma unroll
                for (int j = 0; j < 4; j++) {
                    ag[i][j] += am[i] * gm[j];
                    au[i][j] += am[i] * um[j];
                }
        }
        __syncthreads();
    }

    #pragma unroll
    for (int i = 0; i < 4; i++) {
        int r = row0 + ty * 4 + i;
        size_t base = (size_t)r * F_ + n0 + tx * 4;
        #pragma unroll
        for (int j = 0; j < 4; j++) {
            float g = ag[i][j], u = au[i][j];
            g_act[base + j] = (g / (1.0f + __expf(-g))) * u;
        }
    }
}

__global__ __launch_bounds__(256)
void gemm2_simt(const float* __restrict__ down_w) {
    if (g_flagB) return;
    int row0 = blockIdx.y * SBM;
    if (row0 >= g_pad_off[E_]) return;
    int e = 0;
    while (e < E_ - 1 && g_pad_off[e + 1] <= row0) e++;
    const float* Wd = down_w + (size_t)e * F_ * D_;
    int n0 = blockIdx.x * SBN;

    __shared__ float As2[SBK][SBM + 4];
    __shared__ float Bs2[SBK][SBN];

    int tid   = threadIdx.x;
    int a_row = tid >> 2;
    int a_k   = (tid & 3) * 4;
    size_t abase = (size_t)(row0 + a_row) * F_;

    int b_k = tid >> 4;
    int b_n = (tid & 15) * 4;
    int ty = tid >> 4, tx = tid & 15;

    float acc[4][4] = {};

    for (int k0 = 0; k0 < F_; k0 += SBK) {
        float4 av = *(const float4*)(g_act + abase + k0 + a_k);
        As2[a_k + 0][a_row] = av.x;  As2[a_k + 1][a_row] = av.y;
        As2[a_k + 2][a_row] = av.z;  As2[a_k + 3][a_row] = av.w;
        *(float4*)&Bs2[b_k][b_n] = *(const float4*)(Wd + (size_t)(k0 + b_k) * D_ + n0 + b_n);
        __syncthreads();
        #pragma unroll
        for (int kk = 0; kk < SBK; kk++) {
            float4 a4 = *(const float4*)&As2[kk][ty * 4];
            float4 b4 = *(const float4*)&Bs2[kk][tx * 4];
            float am[4] = {a4.x, a4.y, a4.z, a4.w};
            float bm[4] = {b4.x, b4.y, b4.z, b4.w};
            #pragma unroll
            for (int i = 0; i < 4; i++)
                #pragma unroll
                for (int j = 0; j < 4; j++)
                    acc[i][j] += am[i] * bm[j];
        }
        __syncthreads();
    }

    #pragma unroll
    for (int i = 0; i < 4; i++) {
        int r = row0 + ty * 4 + i;
        float w = g_perm_w[r];
        float* yrow = g_y2 + (size_t)r * D_ + n0 + tx * 4;
        #pragma unroll
        for (int j = 0; j < 4; j++)
            yrow[j] = acc[i][j] * w;
    }
}

// ---------------- combine ----------------
__global__ void combine_kernel(float* __restrict__ out) {
    int i = blockIdx.x * 256 + threadIdx.x;
    if (i >= OUT_ELEMS) return;
    int t = i >> 10, d = i & 1023;
    int s0 = g_tok_slot[t * 2 + 0];
    int s1 = g_tok_slot[t * 2 + 1];
    out[i] = g_y2[(size_t)s0 * D_ + d] + g_y2[(size_t)s1 * D_ + d];
}

// ---------------- launch ----------------
extern "C" void kernel_launch(void* const* d_in, const int* in_sizes, int n_in,
                              void* d_out, int out_size) {
    const float* x      = (const float*)d_in[0];
    const float* rw     = (const float*)d_in[1];
    const float* gate_w = (const float*)d_in[2];
    const float* up_w   = (const float*)d_in[3];
    const float* down_w = (const float*)d_in[4];
    float* out = (float*)d_out;

    static int smem_set = 0;
    if (!smem_set) {
        cudaFuncSetAttribute(gemm1_mma, cudaFuncAttributeMaxDynamicSharedMemorySize, SMEM_DYN);
        cudaFuncSetAttribute(gemm2_mma, cudaFuncAttributeMaxDynamicSharedMemorySize, SMEM_DYN);
        smem_set = 1;
    }

    mma_selftest<<<1, 32>>>();
    init_kernel<<<(PROBE_ACT + 255) / 256, 256>>>();
    router_kernel<<<NTOK, 256>>>(x, rw);
    scan_kernel<<<1, 1>>>();
    fill_kernel<<<(NSLOT + 255) / 256, 256>>>();

    dim3 g1m(F_ / 64, SLOT_PAD / 128);   // 44 x 136
    gemm1_mma<<<g1m, 256, SMEM_DYN>>>(x, gate_w, up_w);
    probeA_kernel<<<(PROBE_ACT + 255) / 256, 256>>>();
    dim3 g1s(F_ / SBN, SLOT_PAD / SBM);
    gemm1_simt<<<g1s, 256>>>(x, gate_w, up_w);

    dim3 g2m(D_ / 128, SLOT_PAD / 128);  // 8 x 136
    gemm2_mma<<<g2m, 256, SMEM_DYN>>>(down_w);
    probeB_kernel<<<(PROBE_Y2 + 255) / 256, 256>>>();
    dim3 g2s(D_ / SBN, SLOT_PAD / SBM);
    gemm2_simt<<<g2s, 256>>>(down_w);

    combine_kernel<<<(OUT_ELEMS + 255) / 256, 256>>>(out);
}

// round 16
// speedup vs baseline: 1.3141x; 1.0356x over previous
#include <cuda_runtime.h>
#include <math.h>
#include <stdint.h>

// ---------------- problem constants ----------------
#define E_        8
#define NTOK      8192
#define D_        1024
#define F_        2816
#define NSLOT     (NTOK * 2)
#define SLOT_PAD  (NSLOT + E_ * 128)   // 17408
#define OUT_ELEMS (NTOK * D_)

#define BK    16                        // K per stage (two m16n8k8 halves)
#define NB    3                         // triple buffer, one sync/stage

// fragment-layout smem sizes (words)
#define ASTG   2112                     // A: 16 groups x 132
#define BSTG1  4224                     // GEMM1 B: 64 blocks x 66 (256 n-slots)
#define BSTG2  2112                     // GEMM2 B: 32 blocks x 66 (128 n-slots)
#define STG1W  (ASTG + BSTG1)           // 6336 words
#define STG2W  (ASTG + BSTG2)           // 4224 words
#define SMEM1  (NB * STG1W * 4)         // 76032 B
#define SMEM2  (NB * STG2W * 4)         // 50688 B

// ---------------- static device scratch ----------------
__device__ __align__(128) float g_act[(size_t)SLOT_PAD * F_];
__device__ __align__(128) float g_y2[(size_t)SLOT_PAD * D_];

__device__ int   g_perm_token[SLOT_PAD];
__device__ float g_perm_w[SLOT_PAD];
__device__ int   g_tok_slot[NSLOT];
__device__ int   g_counts[E_];
__device__ int   g_cursor[E_];
__device__ int   g_pad_off[E_ + 1];
__device__ int   g_topk_idx[NSLOT];
__device__ float g_topk_w[NSLOT];

// ---------------- tf32 mma helpers ----------------
static __device__ __forceinline__ uint32_t f2tf(float v) {
    uint32_t r;
    asm("cvt.rna.tf32.f32 %0, %1;" : "=r"(r) : "f"(v));
    return r;
}
static __device__ __forceinline__ void mma_tf32(float* d, const uint32_t* a, const uint32_t* b) {
    asm volatile("mma.sync.aligned.m16n8k8.row.col.f32.tf32.tf32.f32 "
                 "{%0,%1,%2,%3}, {%4,%5,%6,%7}, {%8,%9}, {%0,%1,%2,%3};"
                 : "+f"(d[0]), "+f"(d[1]), "+f"(d[2]), "+f"(d[3])
                 : "r"(a[0]), "r"(a[1]), "r"(a[2]), "r"(a[3]), "r"(b[0]), "r"(b[1]));
}

// ---------------- init ----------------
__global__ void init_kernel() {
    int i = blockIdx.x * 256 + threadIdx.x;
    if (i < SLOT_PAD) { g_perm_token[i] = -1; g_perm_w[i] = 0.0f; }
    if (i < E_) g_counts[i] = 0;
}

// ---------------- router / scan / fill ----------------
__global__ void router_kernel(const float* __restrict__ x, const float* __restrict__ rw) {
    int t = blockIdx.x;
    const float* xr = x + (size_t)t * D_;
    int lane = threadIdx.x & 31;
    int w    = threadIdx.x >> 5;

    double s = 0.0;
    for (int d = lane; d < D_; d += 32)
        s += (double)xr[d] * (double)rw[d * E_ + w];
    #pragma unroll
    for (int o = 16; o > 0; o >>= 1)
        s += __shfl_down_sync(0xffffffffu, s, o);

    __shared__ double sc[E_];
    if (lane == 0) sc[w] = s;
    __syncthreads();

    if (threadIdx.x == 0) {
        double m = sc[0];
        #pragma unroll
        for (int e = 1; e < E_; e++) m = fmax(m, sc[e]);
        double p[E_], sum = 0.0;
        #pragma unroll
        for (int e = 0; e < E_; e++) { p[e] = exp(sc[e] - m); sum += p[e]; }
        #pragma unroll
        for (int e = 0; e < E_; e++) p[e] /= sum;
        int i0 = 0;
        #pragma unroll
        for (int e = 1; e < E_; e++) if (p[e] > p[i0]) i0 = e;
        int i1 = (i0 == 0) ? 1 : 0;
        #pragma unroll
        for (int e = 0; e < E_; e++) { if (e == i0) continue; if (p[e] > p[i1]) i1 = e; }
        float p0 = (float)p[i0], p1 = (float)p[i1];
        float inv = 1.0f / (p0 + p1);
        g_topk_idx[t * 2 + 0] = i0;  g_topk_idx[t * 2 + 1] = i1;
        g_topk_w[t * 2 + 0] = p0 * inv;  g_topk_w[t * 2 + 1] = p1 * inv;
        atomicAdd(&g_counts[i0], 1);
        atomicAdd(&g_counts[i1], 1);
    }
}

__global__ void scan_kernel() {
    int off = 0;
    #pragma unroll
    for (int e = 0; e < E_; e++) {
        g_pad_off[e] = off;  g_cursor[e] = off;
        off += (g_counts[e] + 127) & ~127;
    }
    g_pad_off[E_] = off;
}

__global__ void fill_kernel() {
    int idx = blockIdx.x * blockDim.x + threadIdx.x;
    if (idx >= NSLOT) return;
    int e    = g_topk_idx[idx];
    int slot = atomicAdd(&g_cursor[e], 1);
    g_perm_token[slot] = idx >> 1;
    g_perm_w[slot]     = g_topk_w[idx];
    g_tok_slot[idx]    = slot;
}

// ---------------- fragment-layout store helpers ----------------
// A value (m,k): group=(k>>3)*8+(m>>4); lane=4*(m&7)+(k&3);
//   line=lane^(lane>>3); q=((m>>3)&1)+2*((k>>2)&1); addr=group*132+line*4+q
// one float4 at (am, ak4..ak4+3)
static __device__ __forceinline__ void store_a4(uint32_t* An, int am, int ak4,
                                                const float* a) {
    int g0 = ((ak4 >> 3) * 8 + (am >> 4)) * 132;
    int q  = ((am >> 3) & 1) + 2 * ((ak4 >> 2) & 1);
    int lb = 4 * (am & 7);
    #pragma unroll
    for (int j = 0; j < 4; j++) {
        int lane = lb + j;
        int line = lane ^ (lane >> 3);
        An[g0 + line * 4 + q] = f2tf(a[j]);
    }
}
// B values (k rows bkr & bkr+8, slots ns..ns+3); HS = words per k-half
static __device__ __forceinline__ void store_b8(uint32_t* Bn, int bkr, int ns0,
                                                const float* b0, const float* b1,
                                                int HS) {
    int klow = bkr & 3;
    int cB   = bkr >> 2;
    #pragma unroll
    for (int t = 0; t < 4; t++) {
        int ns   = ns0 + t;
        int lane = 4 * (ns & 7) + klow;
        int blk  = (ns >> 3) * 66;
        Bn[blk + 2 * lane + cB]      = f2tf(b0[t]);
        Bn[HS + blk + 2 * lane + cB] = f2tf(b1[t]);
    }
}

// =====================================================================
// GEMM1 (tf32 mma): act = silu(x@G) * (x@U)
// CTA 128m x 128f (B: 256 n-slots = gate|up). 512 threads, 16 warps:
// wm=wid>>2 (32m each), wn=wid&3 (32f each, gate+up fused).
// =====================================================================
__global__ __launch_bounds__(512, 1)
void gemm1_mma(const float* __restrict__ x,
               const float* __restrict__ gate_w,
               const float* __restrict__ up_w) {
    int row0 = blockIdx.y * 128;
    if (row0 >= g_pad_off[E_]) return;
    int e = 0;
    while (e < E_ - 1 && g_pad_off[e + 1] <= row0) e++;
    int f0  = blockIdx.x * 128;
    int tid = threadIdx.x, wid = tid >> 5, lane = tid & 31;
    int wm = wid >> 2, wn = wid & 3;

    extern __shared__ uint32_t dyn[];

    // A loader: am = tid>>2 (0..127), ak4 = (tid&3)*4 -> one float4
    int am  = tid >> 2;
    int ak4 = (tid & 3) * 4;
    int tok = g_perm_token[row0 + am];
    bool valid = (tok >= 0);
    const float* pa = x + (size_t)(valid ? tok : 0) * D_ + ak4;

    // B loader: bkr = tid>>6 (0..7), bn4 = (tid&63)*4 (0..252 slots)
    int bkr = tid >> 6;
    int bn4 = (tid & 63) * 4;
    const float* pb = (bn4 < 128)
        ? gate_w + ((size_t)e * D_ + bkr) * F_ + f0 + bn4
        : up_w   + ((size_t)e * D_ + bkr) * F_ + f0 + (bn4 - 128);

    float accG[2][4][4], accU[2][4][4];
    #pragma unroll
    for (int i = 0; i < 2; i++)
        #pragma unroll
        for (int j = 0; j < 4; j++)
            #pragma unroll
            for (int q = 0; q < 4; q++) { accG[i][j][q] = 0.f; accU[i][j][q] = 0.f; }

    const int NS = D_ / BK;   // 64

    float4 rA, rB0, rB1;
    rA  = valid ? *(const float4*)pa : make_float4(0, 0, 0, 0);
    rB0 = *(const float4*)pb;
    rB1 = *(const float4*)(pb + (size_t)8 * F_);
    store_a4(dyn, am, ak4, (const float*)&rA);
    store_b8(dyn + ASTG, bkr, bn4, (const float*)&rB0, (const float*)&rB1, 32 * 66);
    rA  = valid ? *(const float4*)(pa + BK) : make_float4(0, 0, 0, 0);
    rB0 = *(const float4*)(pb + (size_t)BK * F_);
    rB1 = *(const float4*)(pb + (size_t)(BK + 8) * F_);
    __syncthreads();

    int lineoff = (lane ^ (lane >> 3)) * 4;
    int boff    = 2 * lane;

    #pragma unroll 1
    for (int s = 0; s < NS; s++) {
        int cb = s % NB;
        if (s + 1 < NS) {
            uint32_t* stg = dyn + ((s + 1) % NB) * STG1W;
            store_a4(stg, am, ak4, (const float*)&rA);
            store_b8(stg + ASTG, bkr, bn4, (const float*)&rB0, (const float*)&rB1, 32 * 66);
        }
        if (s + 2 < NS) {
            int k0 = (s + 2) * BK;
            rA  = valid ? *(const float4*)(pa + k0) : make_float4(0, 0, 0, 0);
            rB0 = *(const float4*)(pb + (size_t)k0 * F_);
            rB1 = *(const float4*)(pb + (size_t)(k0 + 8) * F_);
        }
        __syncthreads();

        const uint32_t* A = dyn + cb * STG1W;
        const uint32_t* B = A + ASTG;
        #pragma unroll
        for (int h = 0; h < 2; h++) {
            uint4 af[2];
            #pragma unroll
            for (int i = 0; i < 2; i++)
                af[i] = *(const uint4*)&A[(h * 8 + 2 * wm + i) * 132 + lineoff];
            #pragma unroll
            for (int j = 0; j < 4; j++) {
                uint2 bgv = *(const uint2*)&B[(h * 32 + 4 * wn + j) * 66 + boff];
                uint2 buv = *(const uint2*)&B[(h * 32 + 16 + 4 * wn + j) * 66 + boff];
                #pragma unroll
                for (int i = 0; i < 2; i++) {
                    mma_tf32(accG[i][j], (const uint32_t*)&af[i], (const uint32_t*)&bgv);
                    mma_tf32(accU[i][j], (const uint32_t*)&af[i], (const uint32_t*)&buv);
                }
            }
        }
    }

    // epilogue: SwiGLU, fp32 act
    #pragma unroll
    for (int i = 0; i < 2; i++)
        #pragma unroll
        for (int j = 0; j < 4; j++) {
            int fb = f0 + 32 * wn + 8 * j + 2 * (lane & 3);
            #pragma unroll
            for (int h = 0; h < 2; h++) {
                int row = row0 + 32 * wm + 16 * i + (lane >> 2) + 8 * h;
                float g0 = accG[i][j][2 * h + 0], g1 = accG[i][j][2 * h + 1];
                float u0 = accU[i][j][2 * h + 0], u1 = accU[i][j][2 * h + 1];
                float2 o;
                o.x = (g0 / (1.0f + __expf(-g0))) * u0;
                o.y = (g1 / (1.0f + __expf(-g1))) * u1;
                *(float2*)(g_act + (size_t)row * F_ + fb) = o;
            }
        }
}

// =====================================================================
// GEMM2 (tf32 mma, fragment layout): y2 = w * (act @ Wdown)
// CTA 128m x 128n, 256 threads. warps: wm=wid>>1 (32m), wn=wid&1 (64n).
// =====================================================================
__global__ __launch_bounds__(256, 2)
void gemm2_mma(const float* __restrict__ down_w) {
    int row0 = blockIdx.y * 128;
    if (row0 >= g_pad_off[E_]) return;
    int e = 0;
    while (e < E_ - 1 && g_pad_off[e + 1] <= row0) e++;
    int n0  = blockIdx.x * 128;
    int tid = threadIdx.x, wid = tid >> 5, lane = tid & 31;
    int wm = wid >> 1, wn = wid & 1;

    extern __shared__ uint32_t dyn[];

    // A loader: am = tid>>1, akq = (tid&1)*4; covers k..k+3 and k+8..k+11
    int am  = tid >> 1;
    int akq = (tid & 1) * 4;
    const float* pa = g_act + (size_t)(row0 + am) * F_ + akq;

    int bkr = tid >> 5;
    int bn4 = (tid & 31) * 4;
    const float* pb = down_w + ((size_t)e * F_ + bkr) * D_ + n0 + bn4;

    float acc[2][8][4];
    #pragma unroll
    for (int i = 0; i < 2; i++)
        #pragma unroll
        for (int j = 0; j < 8; j++)
            #pragma unroll
            for (int q = 0; q < 4; q++) acc[i][j][q] = 0.f;

    const int NS = F_ / BK;   // 176

    float4 rA0, rA1, rB0, rB1;
    rA0 = *(const float4*)pa;
    rA1 = *(const float4*)(pa + 8);
    rB0 = *(const float4*)pb;
    rB1 = *(const float4*)(pb + (size_t)8 * D_);
    store_a4(dyn, am, akq, (const float*)&rA0);
    store_a4(dyn, am, akq + 8, (const float*)&rA1);
    store_b8(dyn + ASTG, bkr, bn4, (const float*)&rB0, (const float*)&rB1, 16 * 66);
    rA0 = *(const float4*)(pa + BK);
    rA1 = *(const float4*)(pa + BK + 8);
    rB0 = *(const float4*)(pb + (size_t)BK * D_);
    rB1 = *(const float4*)(pb + (size_t)(BK + 8) * D_);
    __syncthreads();

    int lineoff = (lane ^ (lane >> 3)) * 4;
    int boff    = 2 * lane;

    #pragma unroll 1
    for (int s = 0; s < NS; s++) {
        int cb = s % NB;
        if (s + 1 < NS) {
            uint32_t* stg = dyn + ((s + 1) % NB) * STG2W;
            store_a4(stg, am, akq, (const float*)&rA0);
            store_a4(stg, am, akq + 8, (const float*)&rA1);
            store_b8(stg + ASTG, bkr, bn4, (const float*)&rB0, (const float*)&rB1, 16 * 66);
        }
        if (s + 2 < NS) {
            int k0 = (s + 2) * BK;
            rA0 = *(const float4*)(pa + k0);
            rA1 = *(const float4*)(pa + k0 + 8);
            rB0 = *(const float4*)(pb + (size_t)k0 * D_);
            rB1 = *(const float4*)(pb + (size_t)(k0 + 8) * D_);
        }
        __syncthreads();

        const uint32_t* A = dyn + cb * STG2W;
        const uint32_t* B = A + ASTG;
        #pragma unroll
        for (int h = 0; h < 2; h++) {
            uint4 af[2];
            #pragma unroll
            for (int i = 0; i < 2; i++)
                af[i] = *(const uint4*)&A[(h * 8 + 2 * wm + i) * 132 + lineoff];
            #pragma unroll
            for (int j = 0; j < 8; j++) {
                uint2 bv = *(const uint2*)&B[(h * 16 + 8 * wn + j) * 66 + boff];
                #pragma unroll
                for (int i = 0; i < 2; i++)
                    mma_tf32(acc[i][j], (const uint32_t*)&af[i], (const uint32_t*)&bv);
            }
        }
    }

    #pragma unroll
    for (int i = 0; i < 2; i++)
        #pragma unroll
        for (int h = 0; h < 2; h++) {
            int row = row0 + 32 * wm + 16 * i + (lane >> 2) + 8 * h;
            float w = g_perm_w[row];
            #pragma unroll
            for (int j = 0; j < 8; j++) {
                int nn = n0 + 64 * wn + 8 * j + 2 * (lane & 3);
                float2 v;
                v.x = acc[i][j][2 * h + 0] * w;
                v.y = acc[i][j][2 * h + 1] * w;
                *(float2*)(g_y2 + (size_t)row * D_ + nn) = v;
            }
        }
}

// ---------------- combine ----------------
__global__ void combine_kernel(float* __restrict__ out) {
    int i = blockIdx.x * 256 + threadIdx.x;
    if (i >= OUT_ELEMS) return;
    int t = i >> 10, d = i & 1023;
    int s0 = g_tok_slot[t * 2 + 0];
    int s1 = g_tok_slot[t * 2 + 1];
    out[i] = g_y2[(size_t)s0 * D_ + d] + g_y2[(size_t)s1 * D_ + d];
}

// ---------------- launch ----------------
extern "C" void kernel_launch(void* const* d_in, const int* in_sizes, int n_in,
                              void* d_out, int out_size) {
    const float* x      = (const float*)d_in[0];
    const float* rw     = (const float*)d_in[1];
    const float* gate_w = (const float*)d_in[2];
    const float* up_w   = (const float*)d_in[3];
    const float* down_w = (const float*)d_in[4];
    float* out = (float*)d_out;

    static int smem_set = 0;
    if (!smem_set) {
        cudaFuncSetAttribute(gemm1_mma, cudaFuncAttributeMaxDynamicSharedMemorySize, SMEM1);
        cudaFuncSetAttribute(gemm2_mma, cudaFuncAttributeMaxDynamicSharedMemorySize, SMEM2);
        smem_set = 1;
    }

    init_kernel<<<(SLOT_PAD + 255) / 256, 256>>>();
    router_kernel<<<NTOK, 256>>>(x, rw);
    scan_kernel<<<1, 1>>>();
    fill_kernel<<<(NSLOT + 255) / 256, 256>>>();

    dim3 g1(F_ / 128, SLOT_PAD / 128);   // 22 x 136
    gemm1_mma<<<g1, 512, SMEM1>>>(x, gate_w, up_w);

    dim3 g2(D_ / 128, SLOT_PAD / 128);   // 8 x 136
    gemm2_mma<<<g2, 256, SMEM2>>>(down_w);

    combine_kernel<<<(OUT_ELEMS + 255) / 256, 256>>>(out);
}